// round 9
// baseline (speedup 1.0000x reference)
#include <cuda_runtime.h>

// Problem constants (fixed shapes)
#define NB   2
#define NQL  4096
#define NKL  4096
#define NQD  512
#define NCD  768
#define NH   8
#define NDH  64
#define NIN  512            // H * DH
#define ATTN_SCALE 0.125f   // DH^-0.5

// Scratch buffers (static device globals -- allocation-free per harness rules)
__device__ float g_Q[NB * NQL * NIN];
__device__ float g_K[NB * NKL * NIN];
__device__ float g_V[NB * NKL * NIN];
__device__ float g_O[NB * NQL * NIN];

// ---------------------------------------------------------------------------
// Tiled SGEMM: C[M,N] = A[M,K] @ B[K,N] (+ bias broadcast over rows)
// BM=BN=128, BK=8, 256 threads, 8x8 register tile per thread.
// Requires M%128==0, N%128==0, K%8==0 (true for all uses here).
// ---------------------------------------------------------------------------
__global__ __launch_bounds__(256) void sgemm_kernel(
    const float* __restrict__ A, const float* __restrict__ Bm,
    const float* __restrict__ bias, float* __restrict__ C,
    int M, int N, int K)
{
    __shared__ float As[8][128];   // A tile, transposed: As[k][m]
    __shared__ float Bs[8][128];   // B tile: Bs[k][n]

    const int tid    = threadIdx.x;
    const int rowBlk = blockIdx.y << 7;
    const int colBlk = blockIdx.x << 7;

    const int aRow = tid >> 1;          // 0..127
    const int aCol = (tid & 1) << 2;    // 0 or 4
    const int bRow = tid >> 5;          // 0..7
    const int bCol = (tid & 31) << 2;   // 0..124

    const int tr = (tid >> 4) << 3;     // thread row base (0..120)
    const int tc = (tid & 15) << 3;     // thread col base (0..120)

    float acc[8][8];
#pragma unroll
    for (int i = 0; i < 8; i++)
#pragma unroll
        for (int j = 0; j < 8; j++) acc[i][j] = 0.f;

    const float* Ap = A + (long)(rowBlk + aRow) * K + aCol;
    const float* Bp = Bm + (long)bRow * N + colBlk + bCol;

    for (int k0 = 0; k0 < K; k0 += 8) {
        float4 av = *(const float4*)(Ap + k0);
        As[aCol + 0][aRow] = av.x;
        As[aCol + 1][aRow] = av.y;
        As[aCol + 2][aRow] = av.z;
        As[aCol + 3][aRow] = av.w;
        *(float4*)&Bs[bRow][bCol] = *(const float4*)(Bp + (long)k0 * N);
        __syncthreads();

#pragma unroll
        for (int kk = 0; kk < 8; kk++) {
            float ar[8], br[8];
            *(float4*)&ar[0] = *(const float4*)&As[kk][tr];
            *(float4*)&ar[4] = *(const float4*)&As[kk][tr + 4];
            *(float4*)&br[0] = *(const float4*)&Bs[kk][tc];
            *(float4*)&br[4] = *(const float4*)&Bs[kk][tc + 4];
#pragma unroll
            for (int i = 0; i < 8; i++)
#pragma unroll
                for (int j = 0; j < 8; j++)
                    acc[i][j] = fmaf(ar[i], br[j], acc[i][j]);
        }
        __syncthreads();
    }

    float bb[8];
#pragma unroll
    for (int j = 0; j < 8; j++) bb[j] = bias ? bias[colBlk + tc + j] : 0.f;

#pragma unroll
    for (int i = 0; i < 8; i++) {
        float* Cp = C + (long)(rowBlk + tr + i) * N + colBlk + tc;
        float4 o0, o1;
        o0.x = acc[i][0] + bb[0]; o0.y = acc[i][1] + bb[1];
        o0.z = acc[i][2] + bb[2]; o0.w = acc[i][3] + bb[3];
        o1.x = acc[i][4] + bb[4]; o1.y = acc[i][5] + bb[5];
        o1.z = acc[i][6] + bb[6]; o1.w = acc[i][7] + bb[7];
        *(float4*)Cp       = o0;
        *(float4*)(Cp + 4) = o1;
    }
}

// ---------------------------------------------------------------------------
// Flash attention, fp32. One block = 64 queries of one (b, h).
// 128 threads: tx = tid&7 (key/dcol group of 8), ty = tid>>3 (query group of 4).
// Per-thread 4x8 register tiles for S = Q*K^T and O += P*V.
// smem: Qs [d][q] (swizzled), KP = K [d][k] (swizzled) reused as P [q][k]
// (swizzled), Vs [k][d] plain. 3 * 16KB = 48KB static.
// ---------------------------------------------------------------------------
#define SWZ(r, c) ((c) ^ (((r) & 7) << 2))

__global__ __launch_bounds__(128) void attn_kernel(
    const float* __restrict__ Q, const float* __restrict__ K,
    const float* __restrict__ V, float* __restrict__ O)
{
    __shared__ float Qs[64][64];
    __shared__ float KP[64][64];
    __shared__ float Vs[64][64];

    const int tid = threadIdx.x;
    const int tx  = tid & 7;
    const int ty  = tid >> 3;      // 0..15

    const int qt = blockIdx.x;
    const int h  = blockIdx.y;
    const int b  = blockIdx.z;

    const float* Qp = Q + ((long)b * NQL + (long)qt * 64) * NIN + h * NDH;
    const float* Kp = K + (long)b * NKL * NIN + h * NDH;
    const float* Vp = V + (long)b * NKL * NIN + h * NDH;

    // Load Q tile transposed [d][q], pre-scaled, XOR-swizzled
    for (int idx = tid; idx < 64 * 64; idx += 128) {
        int r = idx >> 6, c = idx & 63;
        Qs[c][SWZ(c, r)] = Qp[(long)r * NIN + c] * ATTN_SCALE;
    }

    float o[4][8];
    float m[4], l[4];
#pragma unroll
    for (int r = 0; r < 4; r++) {
        m[r] = -1e30f;
        l[r] = 0.f;
#pragma unroll
        for (int c = 0; c < 8; c++) o[r][c] = 0.f;
    }

    for (int kt = 0; kt < NKL / 64; kt++) {
        const float* Kt = Kp + (long)kt * 64 * NIN;
        const float* Vt = Vp + (long)kt * 64 * NIN;

        __syncthreads();   // previous tile's consumers done (also fences Qs on kt=0)
        for (int idx = tid; idx < 64 * 64; idx += 128) {
            int r = idx >> 6, c = idx & 63;
            KP[c][SWZ(c, r)] = Kt[(long)r * NIN + c];   // K transposed [d][k]
            Vs[r][c]         = Vt[(long)r * NIN + c];   // V [k][d]
        }
        __syncthreads();

        // --- S = (Q*scale) @ K^T : per-thread 4 q-rows x 8 keys ---
        float s[4][8];
#pragma unroll
        for (int r = 0; r < 4; r++)
#pragma unroll
            for (int j = 0; j < 8; j++) s[r][j] = 0.f;

#pragma unroll 8
        for (int d = 0; d < 64; d++) {
            const int sw = (d & 7) << 2;
            float4 q4 = *(const float4*)&Qs[d][(4 * ty) ^ sw];
            float4 k0 = *(const float4*)&KP[d][(8 * tx) ^ sw];
            float4 k1 = *(const float4*)&KP[d][(8 * tx + 4) ^ sw];
            float qq[4] = {q4.x, q4.y, q4.z, q4.w};
            float kk[8] = {k0.x, k0.y, k0.z, k0.w, k1.x, k1.y, k1.z, k1.w};
#pragma unroll
            for (int r = 0; r < 4; r++)
#pragma unroll
                for (int j = 0; j < 8; j++)
                    s[r][j] = fmaf(qq[r], kk[j], s[r][j]);
        }

        // --- online softmax: rows span the 8 tx lanes (lane bits 0..2) ---
#pragma unroll
        for (int r = 0; r < 4; r++) {
            float mt = s[r][0];
#pragma unroll
            for (int j = 1; j < 8; j++) mt = fmaxf(mt, s[r][j]);
            mt = fmaxf(mt, __shfl_xor_sync(0xffffffffu, mt, 1));
            mt = fmaxf(mt, __shfl_xor_sync(0xffffffffu, mt, 2));
            mt = fmaxf(mt, __shfl_xor_sync(0xffffffffu, mt, 4));
            float mn   = fmaxf(m[r], mt);
            float corr = __expf(m[r] - mn);
            float rs = 0.f;
#pragma unroll
            for (int j = 0; j < 8; j++) {
                float p = __expf(s[r][j] - mn);
                s[r][j] = p;
                rs += p;
            }
            rs += __shfl_xor_sync(0xffffffffu, rs, 1);
            rs += __shfl_xor_sync(0xffffffffu, rs, 2);
            rs += __shfl_xor_sync(0xffffffffu, rs, 4);
            l[r] = l[r] * corr + rs;
            m[r] = mn;
#pragma unroll
            for (int c = 0; c < 8; c++) o[r][c] *= corr;
        }

        __syncthreads();   // all K reads done -> reuse KP for P[q][k]
#pragma unroll
        for (int r = 0; r < 4; r++) {
            int q = 4 * ty + r;
            const int sw = (q & 7) << 2;
#pragma unroll
            for (int j = 0; j < 8; j++)
                KP[q][(8 * tx + j) ^ sw] = s[r][j];
        }
        __syncthreads();

        // --- O += P @ V : per-thread 4 q-rows x 8 d-cols ---
#pragma unroll 4
        for (int k = 0; k < 64; k++) {
            float4 v0 = *(const float4*)&Vs[k][8 * tx];
            float4 v1 = *(const float4*)&Vs[k][8 * tx + 4];
            float vv[8] = {v0.x, v0.y, v0.z, v0.w, v1.x, v1.y, v1.z, v1.w};
#pragma unroll
            for (int r = 0; r < 4; r++) {
                int q = 4 * ty + r;
                float p = KP[q][k ^ ((q & 7) << 2)];
#pragma unroll
                for (int c = 0; c < 8; c++)
                    o[r][c] = fmaf(p, vv[c], o[r][c]);
            }
        }
    }

    // Epilogue: normalize and write to [b, q, h*64 + d]
#pragma unroll
    for (int r = 0; r < 4; r++) {
        float inv = 1.f / l[r];
        int q = qt * 64 + 4 * ty + r;
        float* Op = O + ((long)b * NQL + q) * NIN + h * NDH + 8 * tx;
        float4 w0, w1;
        w0.x = o[r][0] * inv; w0.y = o[r][1] * inv;
        w0.z = o[r][2] * inv; w0.w = o[r][3] * inv;
        w1.x = o[r][4] * inv; w1.y = o[r][5] * inv;
        w1.z = o[r][6] * inv; w1.w = o[r][7] * inv;
        *(float4*)Op       = w0;
        *(float4*)(Op + 4) = w1;
    }
}

// ---------------------------------------------------------------------------
// Launch: Q/K/V projections -> flash attention -> output projection (+bias)
// All launches on the default stream; no syncs, no allocation -> capturable.
// ---------------------------------------------------------------------------
extern "C" void kernel_launch(void* const* d_in, const int* in_sizes, int n_in,
                              void* d_out, int out_size)
{
    (void)in_sizes; (void)n_in; (void)out_size;
    const float* x   = (const float*)d_in[0];
    const float* ctx = (const float*)d_in[1];
    const float* Wq  = (const float*)d_in[2];
    const float* Wk  = (const float*)d_in[3];
    const float* Wv  = (const float*)d_in[4];
    const float* Wo  = (const float*)d_in[5];
    const float* bo  = (const float*)d_in[6];
    float* out = (float*)d_out;

    float *Qb, *Kb, *Vb, *Ob;
    cudaGetSymbolAddress((void**)&Qb, g_Q);
    cudaGetSymbolAddress((void**)&Kb, g_K);
    cudaGetSymbolAddress((void**)&Vb, g_V);
    cudaGetSymbolAddress((void**)&Ob, g_O);

    // Projections
    dim3 gq(NIN / 128, (NB * NQL) / 128);
    sgemm_kernel<<<gq, 256>>>(x,   Wq, nullptr, Qb, NB * NQL, NIN, NQD);
    dim3 gk(NIN / 128, (NB * NKL) / 128);
    sgemm_kernel<<<gk, 256>>>(ctx, Wk, nullptr, Kb, NB * NKL, NIN, NCD);
    sgemm_kernel<<<gk, 256>>>(ctx, Wv, nullptr, Vb, NB * NKL, NIN, NCD);

    // Flash attention
    dim3 ga(NQL / 64, NH, NB);
    attn_kernel<<<ga, 128>>>(Qb, Kb, Vb, Ob);

    // Output projection with bias
    dim3 go(NQD / 128, (NB * NQL) / 128);
    sgemm_kernel<<<go, 256>>>(Ob, Wo, bo, out, NB * NQL, NQD, NIN);
}

// round 10
// speedup vs baseline: 2.5312x; 2.5312x over previous
#include <cuda_runtime.h>
#include <cuda_bf16.h>

// Problem constants (fixed shapes)
#define NB   2
#define NQL  4096
#define NKL  4096
#define NQD  512
#define NCD  768
#define NH   8
#define NDH  64
#define NIN  512            // H * DH
#define ATTN_SCALE 0.125f   // DH^-0.5

#define NELEM (NB * NQL * NIN)   // 8M elements (QL == KL here)

// Scratch (static device globals -- allocation-free per harness rules)
__device__ float g_Q[NELEM];
__device__ float g_K[NELEM];
__device__ float g_V[NELEM];
__device__ float g_O[NELEM];
__device__ __nv_bfloat16 g_Qh[NELEM];
__device__ __nv_bfloat16 g_Ql[NELEM];
__device__ __nv_bfloat16 g_Kh[NELEM];
__device__ __nv_bfloat16 g_Kl[NELEM];
__device__ __nv_bfloat16 g_Vh[NELEM];   // transposed: [b][h][d][k]
__device__ __nv_bfloat16 g_Vl[NELEM];

// ---------------------------------------------------------------------------
// Tiled FFMA SGEMM (unchanged from R9): C[M,N] = A[M,K] @ B[K,N] (+ bias)
// ---------------------------------------------------------------------------
__global__ __launch_bounds__(256) void sgemm_kernel(
    const float* __restrict__ A, const float* __restrict__ Bm,
    const float* __restrict__ bias, float* __restrict__ C,
    int M, int N, int K)
{
    __shared__ float As[8][128];
    __shared__ float Bs[8][128];

    const int tid    = threadIdx.x;
    const int rowBlk = blockIdx.y << 7;
    const int colBlk = blockIdx.x << 7;

    const int aRow = tid >> 1;
    const int aCol = (tid & 1) << 2;
    const int bRow = tid >> 5;
    const int bCol = (tid & 31) << 2;

    const int tr = (tid >> 4) << 3;
    const int tc = (tid & 15) << 3;

    float acc[8][8];
#pragma unroll
    for (int i = 0; i < 8; i++)
#pragma unroll
        for (int j = 0; j < 8; j++) acc[i][j] = 0.f;

    const float* Ap = A + (long)(rowBlk + aRow) * K + aCol;
    const float* Bp = Bm + (long)bRow * N + colBlk + bCol;

    for (int k0 = 0; k0 < K; k0 += 8) {
        float4 av = *(const float4*)(Ap + k0);
        As[aCol + 0][aRow] = av.x;
        As[aCol + 1][aRow] = av.y;
        As[aCol + 2][aRow] = av.z;
        As[aCol + 3][aRow] = av.w;
        *(float4*)&Bs[bRow][bCol] = *(const float4*)(Bp + (long)k0 * N);
        __syncthreads();

#pragma unroll
        for (int kk = 0; kk < 8; kk++) {
            float ar[8], br[8];
            *(float4*)&ar[0] = *(const float4*)&As[kk][tr];
            *(float4*)&ar[4] = *(const float4*)&As[kk][tr + 4];
            *(float4*)&br[0] = *(const float4*)&Bs[kk][tc];
            *(float4*)&br[4] = *(const float4*)&Bs[kk][tc + 4];
#pragma unroll
            for (int i = 0; i < 8; i++)
#pragma unroll
                for (int j = 0; j < 8; j++)
                    acc[i][j] = fmaf(ar[i], br[j], acc[i][j]);
        }
        __syncthreads();
    }

    float bb[8];
#pragma unroll
    for (int j = 0; j < 8; j++) bb[j] = bias ? bias[colBlk + tc + j] : 0.f;

#pragma unroll
    for (int i = 0; i < 8; i++) {
        float* Cp = C + (long)(rowBlk + tr + i) * N + colBlk + tc;
        float4 o0, o1;
        o0.x = acc[i][0] + bb[0]; o0.y = acc[i][1] + bb[1];
        o0.z = acc[i][2] + bb[2]; o0.w = acc[i][3] + bb[3];
        o1.x = acc[i][4] + bb[4]; o1.y = acc[i][5] + bb[5];
        o1.z = acc[i][6] + bb[6]; o1.w = acc[i][7] + bb[7];
        *(float4*)Cp       = o0;
        *(float4*)(Cp + 4) = o1;
    }
}

// ---------------------------------------------------------------------------
// fp32 -> bf16 hi/lo split (elementwise, optional scale), float4-vectorized
// ---------------------------------------------------------------------------
__global__ __launch_bounds__(256) void split_kernel(
    const float* __restrict__ in, __nv_bfloat16* __restrict__ hi,
    __nv_bfloat16* __restrict__ lo, int n4, float scale)
{
    int i = blockIdx.x * 256 + threadIdx.x;
    if (i >= n4) return;
    float4 v = ((const float4*)in)[i];
    float f[4] = {v.x * scale, v.y * scale, v.z * scale, v.w * scale};
    __nv_bfloat162 H0, H1, L0, L1;
    H0.x = __float2bfloat16(f[0]); H0.y = __float2bfloat16(f[1]);
    H1.x = __float2bfloat16(f[2]); H1.y = __float2bfloat16(f[3]);
    L0.x = __float2bfloat16(f[0] - __bfloat162float(H0.x));
    L0.y = __float2bfloat16(f[1] - __bfloat162float(H0.y));
    L1.x = __float2bfloat16(f[2] - __bfloat162float(H1.x));
    L1.y = __float2bfloat16(f[3] - __bfloat162float(H1.y));
    uint2 uh, ul;
    uh.x = *(unsigned*)&H0; uh.y = *(unsigned*)&H1;
    ul.x = *(unsigned*)&L0; ul.y = *(unsigned*)&L1;
    ((uint2*)hi)[i] = uh;
    ((uint2*)lo)[i] = ul;
}

// ---------------------------------------------------------------------------
// V transpose + split: g_V[b][k][h*64+d] -> Vt[b][h][d][k] (bf16 hi/lo)
// 32x32 tiles via smem; coalesced on both sides.
// ---------------------------------------------------------------------------
__global__ __launch_bounds__(256) void vsplit_kernel(
    const float* __restrict__ V, __nv_bfloat16* __restrict__ vh,
    __nv_bfloat16* __restrict__ vl)
{
    __shared__ float tile[32][33];
    const int k0 = blockIdx.x * 32, d0 = blockIdx.y * 32, bh = blockIdx.z;
    const int b = bh >> 3, h = bh & 7;
    const float* src = V + (long)b * NKL * NIN + h * NDH;

    for (int yy = threadIdx.y; yy < 32; yy += 8)
        tile[yy][threadIdx.x] = src[(long)(k0 + yy) * NIN + d0 + threadIdx.x];
    __syncthreads();

    const long obase = (long)bh * NDH * NKL;
    for (int yy = threadIdx.y; yy < 32; yy += 8) {
        float x = tile[threadIdx.x][yy];
        long oidx = obase + (long)(d0 + yy) * NKL + k0 + threadIdx.x;
        __nv_bfloat16 hh = __float2bfloat16(x);
        vh[oidx] = hh;
        vl[oidx] = __float2bfloat16(x - __bfloat162float(hh));
    }
}

// ---------------------------------------------------------------------------
// bf16-split flash attention on mma.sync.m16n8k16 (HMMA)
// Block = 64 q of one (b,h); 4 warps, each warp a 16-q slab.
// S = Qh*Kh + Qh*Kl + Ql*Kh ; O += Ph*Vh + Ph*Vl + Pl*Vh (fp32 accumulate)
// Q fragments cached in registers across the whole key loop.
// P fragments built register-to-register from the S accumulator fragments.
// smem rows padded to 72 bf16 -> fragment LDS banks = (4g+t), conflict-free.
// ---------------------------------------------------------------------------
__device__ __forceinline__ void mma_bf16(float d[4], const unsigned a[4],
                                         unsigned b0, unsigned b1)
{
    asm volatile(
        "mma.sync.aligned.m16n8k16.row.col.f32.bf16.bf16.f32 "
        "{%0,%1,%2,%3}, {%4,%5,%6,%7}, {%8,%9}, {%0,%1,%2,%3};"
        : "+f"(d[0]), "+f"(d[1]), "+f"(d[2]), "+f"(d[3])
        : "r"(a[0]), "r"(a[1]), "r"(a[2]), "r"(a[3]), "r"(b0), "r"(b1));
}

__global__ __launch_bounds__(128) void attn_mma_kernel(
    const __nv_bfloat16* __restrict__ Qh, const __nv_bfloat16* __restrict__ Ql,
    const __nv_bfloat16* __restrict__ Kh, const __nv_bfloat16* __restrict__ Kl,
    const __nv_bfloat16* __restrict__ Vh, const __nv_bfloat16* __restrict__ Vl,
    float* __restrict__ O)
{
    __shared__ __nv_bfloat16 sKh[64][72];
    __shared__ __nv_bfloat16 sKl[64][72];
    __shared__ __nv_bfloat16 sVh[64][72];   // V transposed: [d][k]
    __shared__ __nv_bfloat16 sVl[64][72];

    const int tid  = threadIdx.x;
    const int lane = tid & 31;
    const int w    = tid >> 5;
    const int g    = lane >> 2;   // fragment group row
    const int t    = lane & 3;    // fragment thread-in-group

    const int qt = blockIdx.x, h = blockIdx.y, b = blockIdx.z;

    // ---- Q fragments in registers (constant across key loop) ----
    unsigned qfh[4][4], qfl[4][4];
    {
        const long qoff = ((long)(b * NQL + qt * 64 + w * 16)) * NIN + h * NDH;
        const __nv_bfloat16* qh = Qh + qoff;
        const __nv_bfloat16* ql = Ql + qoff;
#pragma unroll
        for (int j = 0; j < 4; j++) {
            int d0 = 16 * j + 2 * t;
            qfh[j][0] = *(const unsigned*)(qh + (long)g * NIN + d0);
            qfh[j][1] = *(const unsigned*)(qh + (long)(g + 8) * NIN + d0);
            qfh[j][2] = *(const unsigned*)(qh + (long)g * NIN + d0 + 8);
            qfh[j][3] = *(const unsigned*)(qh + (long)(g + 8) * NIN + d0 + 8);
            qfl[j][0] = *(const unsigned*)(ql + (long)g * NIN + d0);
            qfl[j][1] = *(const unsigned*)(ql + (long)(g + 8) * NIN + d0);
            qfl[j][2] = *(const unsigned*)(ql + (long)g * NIN + d0 + 8);
            qfl[j][3] = *(const unsigned*)(ql + (long)(g + 8) * NIN + d0 + 8);
        }
    }

    float o[8][4];
#pragma unroll
    for (int ct = 0; ct < 8; ct++)
#pragma unroll
        for (int e = 0; e < 4; e++) o[ct][e] = 0.f;
    float m0 = -1e30f, m1 = -1e30f, l0 = 0.f, l1 = 0.f;

    const __nv_bfloat16* kbh = Kh + (long)b * NKL * NIN + h * NDH;
    const __nv_bfloat16* kbl = Kl + (long)b * NKL * NIN + h * NDH;
    const __nv_bfloat16* vbh = Vh + (long)(b * NH + h) * NDH * NKL;
    const __nv_bfloat16* vbl = Vl + (long)(b * NH + h) * NDH * NKL;

    for (int kt = 0; kt < NKL / 64; kt++) {
        __syncthreads();   // previous tile's consumers done
        // ---- load K / Vt tiles (16B chunks, coalesced) ----
#pragma unroll
        for (int i = 0; i < 4; i++) {
            int c  = tid + 128 * i;
            int r  = c >> 3, c8 = c & 7;
            long koff = (long)(kt * 64 + r) * NIN + c8 * 8;
            long voff = (long)r * NKL + kt * 64 + c8 * 8;
            *(uint4*)&sKh[r][c8 * 8] = *(const uint4*)(kbh + koff);
            *(uint4*)&sKl[r][c8 * 8] = *(const uint4*)(kbl + koff);
            *(uint4*)&sVh[r][c8 * 8] = *(const uint4*)(vbh + voff);
            *(uint4*)&sVl[r][c8 * 8] = *(const uint4*)(vbl + voff);
        }
        __syncthreads();

        // ---- S = Q @ K^T (bf16x3) ----
        float s[8][4];
#pragma unroll
        for (int nt = 0; nt < 8; nt++) {
            s[nt][0] = s[nt][1] = s[nt][2] = s[nt][3] = 0.f;
#pragma unroll
            for (int j = 0; j < 4; j++) {
                int row = 8 * nt + g, col = 16 * j + 2 * t;
                unsigned bh0 = *(const unsigned*)&sKh[row][col];
                unsigned bh1 = *(const unsigned*)&sKh[row][col + 8];
                unsigned bl0 = *(const unsigned*)&sKl[row][col];
                unsigned bl1 = *(const unsigned*)&sKl[row][col + 8];
                mma_bf16(s[nt], qfh[j], bh0, bh1);
                mma_bf16(s[nt], qfh[j], bl0, bl1);
                mma_bf16(s[nt], qfl[j], bh0, bh1);
            }
        }

        // ---- online softmax (rows g and g+8; reduce over 4 t-lanes) ----
        float mt0 = -1e30f, mt1 = -1e30f;
#pragma unroll
        for (int nt = 0; nt < 8; nt++) {
            mt0 = fmaxf(mt0, fmaxf(s[nt][0], s[nt][1]));
            mt1 = fmaxf(mt1, fmaxf(s[nt][2], s[nt][3]));
        }
        mt0 = fmaxf(mt0, __shfl_xor_sync(0xffffffffu, mt0, 1));
        mt0 = fmaxf(mt0, __shfl_xor_sync(0xffffffffu, mt0, 2));
        mt1 = fmaxf(mt1, __shfl_xor_sync(0xffffffffu, mt1, 1));
        mt1 = fmaxf(mt1, __shfl_xor_sync(0xffffffffu, mt1, 2));
        float mn0 = fmaxf(m0, mt0), mn1 = fmaxf(m1, mt1);
        float cr0 = __expf(m0 - mn0), cr1 = __expf(m1 - mn1);
        m0 = mn0; m1 = mn1;

        float rs0 = 0.f, rs1 = 0.f;
        unsigned ph[8][2], pl[8][2];
#pragma unroll
        for (int nt = 0; nt < 8; nt++) {
            float p0 = __expf(s[nt][0] - m0), p1 = __expf(s[nt][1] - m0);
            float p2 = __expf(s[nt][2] - m1), p3 = __expf(s[nt][3] - m1);
            rs0 += p0 + p1; rs1 += p2 + p3;
            __nv_bfloat162 H, L;
            H.x = __float2bfloat16(p0); H.y = __float2bfloat16(p1);
            L.x = __float2bfloat16(p0 - __bfloat162float(H.x));
            L.y = __float2bfloat16(p1 - __bfloat162float(H.y));
            ph[nt][0] = *(unsigned*)&H; pl[nt][0] = *(unsigned*)&L;
            H.x = __float2bfloat16(p2); H.y = __float2bfloat16(p3);
            L.x = __float2bfloat16(p2 - __bfloat162float(H.x));
            L.y = __float2bfloat16(p3 - __bfloat162float(H.y));
            ph[nt][1] = *(unsigned*)&H; pl[nt][1] = *(unsigned*)&L;
        }
        rs0 += __shfl_xor_sync(0xffffffffu, rs0, 1);
        rs0 += __shfl_xor_sync(0xffffffffu, rs0, 2);
        rs1 += __shfl_xor_sync(0xffffffffu, rs1, 1);
        rs1 += __shfl_xor_sync(0xffffffffu, rs1, 2);
        l0 = l0 * cr0 + rs0;
        l1 = l1 * cr1 + rs1;
#pragma unroll
        for (int ct = 0; ct < 8; ct++) {
            o[ct][0] *= cr0; o[ct][1] *= cr0;
            o[ct][2] *= cr1; o[ct][3] *= cr1;
        }

        // ---- O += P @ V (bf16x3); P A-frags direct from S frags ----
#pragma unroll
        for (int j = 0; j < 4; j++) {
            unsigned ah[4] = {ph[2 * j][0], ph[2 * j][1],
                              ph[2 * j + 1][0], ph[2 * j + 1][1]};
            unsigned al[4] = {pl[2 * j][0], pl[2 * j][1],
                              pl[2 * j + 1][0], pl[2 * j + 1][1]};
#pragma unroll
            for (int ct = 0; ct < 8; ct++) {
                int row = 8 * ct + g, col = 16 * j + 2 * t;
                unsigned vh0 = *(const unsigned*)&sVh[row][col];
                unsigned vh1 = *(const unsigned*)&sVh[row][col + 8];
                unsigned vl0 = *(const unsigned*)&sVl[row][col];
                unsigned vl1 = *(const unsigned*)&sVl[row][col + 8];
                mma_bf16(o[ct], ah, vh0, vh1);
                mma_bf16(o[ct], ah, vl0, vl1);
                mma_bf16(o[ct], al, vh0, vh1);
            }
        }
    }

    // ---- epilogue: normalize, write g_O[b][q][h*64 + c] ----
    float i0 = 1.f / l0, i1 = 1.f / l1;
    float* op = O + ((long)(b * NQL + qt * 64 + w * 16)) * NIN + h * NDH;
#pragma unroll
    for (int ct = 0; ct < 8; ct++) {
        int cc = 8 * ct + 2 * t;
        float2 w0, w1;
        w0.x = o[ct][0] * i0; w0.y = o[ct][1] * i0;
        w1.x = o[ct][2] * i1; w1.y = o[ct][3] * i1;
        *(float2*)(op + (long)g * NIN + cc)       = w0;
        *(float2*)(op + (long)(g + 8) * NIN + cc) = w1;
    }
}

// ---------------------------------------------------------------------------
// Launch pipeline (graph-capturable: kernel launches only)
// ---------------------------------------------------------------------------
extern "C" void kernel_launch(void* const* d_in, const int* in_sizes, int n_in,
                              void* d_out, int out_size)
{
    (void)in_sizes; (void)n_in; (void)out_size;
    const float* x   = (const float*)d_in[0];
    const float* ctx = (const float*)d_in[1];
    const float* Wq  = (const float*)d_in[2];
    const float* Wk  = (const float*)d_in[3];
    const float* Wv  = (const float*)d_in[4];
    const float* Wo  = (const float*)d_in[5];
    const float* bo  = (const float*)d_in[6];
    float* out = (float*)d_out;

    float *Qf, *Kf, *Vf, *Of;
    __nv_bfloat16 *Qh, *Ql, *Kh, *Kl, *Vh, *Vl;
    cudaGetSymbolAddress((void**)&Qf, g_Q);
    cudaGetSymbolAddress((void**)&Kf, g_K);
    cudaGetSymbolAddress((void**)&Vf, g_V);
    cudaGetSymbolAddress((void**)&Of, g_O);
    cudaGetSymbolAddress((void**)&Qh, g_Qh);
    cudaGetSymbolAddress((void**)&Ql, g_Ql);
    cudaGetSymbolAddress((void**)&Kh, g_Kh);
    cudaGetSymbolAddress((void**)&Kl, g_Kl);
    cudaGetSymbolAddress((void**)&Vh, g_Vh);
    cudaGetSymbolAddress((void**)&Vl, g_Vl);

    // Projections (FFMA SGEMM)
    dim3 gq(NIN / 128, (NB * NQL) / 128);
    sgemm_kernel<<<gq, 256>>>(x,   Wq, nullptr, Qf, NB * NQL, NIN, NQD);
    dim3 gk(NIN / 128, (NB * NKL) / 128);
    sgemm_kernel<<<gk, 256>>>(ctx, Wk, nullptr, Kf, NB * NKL, NIN, NCD);
    sgemm_kernel<<<gk, 256>>>(ctx, Wv, nullptr, Vf, NB * NKL, NIN, NCD);

    // bf16 hi/lo splits (Q pre-scaled by DH^-0.5), V transposed per head
    const int n4 = NELEM / 4;
    split_kernel<<<(n4 + 255) / 256, 256>>>(Qf, Qh, Ql, n4, ATTN_SCALE);
    split_kernel<<<(n4 + 255) / 256, 256>>>(Kf, Kh, Kl, n4, 1.0f);
    dim3 gv(NKL / 32, NDH / 32, NB * NH);
    vsplit_kernel<<<gv, dim3(32, 8)>>>(Vf, Vh, Vl);

    // Flash attention on tensor cores
    dim3 ga(NQL / 64, NH, NB);
    attn_mma_kernel<<<ga, 128>>>(Qh, Ql, Kh, Kl, Vh, Vl, Of);

    // Output projection with bias
    dim3 go(NQD / 128, (NB * NQL) / 128);
    sgemm_kernel<<<go, 256>>>(Of, Wo, bo, out, NB * NQL, NQD, NIN);
}

// round 11
// speedup vs baseline: 2.5417x; 1.0042x over previous
#include <cuda_runtime.h>
#include <cuda_bf16.h>

// Problem constants (fixed shapes)
#define NB   2
#define NQL  4096
#define NKL  4096
#define NQD  512
#define NCD  768
#define NH   8
#define NDH  64
#define NIN  512            // H * DH
#define ATTN_SCALE 0.125f   // DH^-0.5

#define NELEM (NB * NQL * NIN)   // 8M elements (QL == KL here)

// Scratch (static device globals -- allocation-free per harness rules)
__device__ float g_Q[NELEM];
__device__ float g_K[NELEM];
__device__ float g_V[NELEM];
__device__ float g_O[NELEM];
__device__ __nv_bfloat16 g_Qh[NELEM];
__device__ __nv_bfloat16 g_Ql[NELEM];
__device__ __nv_bfloat16 g_Kh[NELEM];
__device__ __nv_bfloat16 g_Kl[NELEM];
__device__ __nv_bfloat16 g_Vh[NELEM];   // transposed: [b][h][d][k]
__device__ __nv_bfloat16 g_Vl[NELEM];

// ---------------------------------------------------------------------------
// Tiled FFMA SGEMM (unchanged from R9): C[M,N] = A[M,K] @ B[K,N] (+ bias)
// ---------------------------------------------------------------------------
__global__ __launch_bounds__(256) void sgemm_kernel(
    const float* __restrict__ A, const float* __restrict__ Bm,
    const float* __restrict__ bias, float* __restrict__ C,
    int M, int N, int K)
{
    __shared__ float As[8][128];
    __shared__ float Bs[8][128];

    const int tid    = threadIdx.x;
    const int rowBlk = blockIdx.y << 7;
    const int colBlk = blockIdx.x << 7;

    const int aRow = tid >> 1;
    const int aCol = (tid & 1) << 2;
    const int bRow = tid >> 5;
    const int bCol = (tid & 31) << 2;

    const int tr = (tid >> 4) << 3;
    const int tc = (tid & 15) << 3;

    float acc[8][8];
#pragma unroll
    for (int i = 0; i < 8; i++)
#pragma unroll
        for (int j = 0; j < 8; j++) acc[i][j] = 0.f;

    const float* Ap = A + (long)(rowBlk + aRow) * K + aCol;
    const float* Bp = Bm + (long)bRow * N + colBlk + bCol;

    for (int k0 = 0; k0 < K; k0 += 8) {
        float4 av = *(const float4*)(Ap + k0);
        As[aCol + 0][aRow] = av.x;
        As[aCol + 1][aRow] = av.y;
        As[aCol + 2][aRow] = av.z;
        As[aCol + 3][aRow] = av.w;
        *(float4*)&Bs[bRow][bCol] = *(const float4*)(Bp + (long)k0 * N);
        __syncthreads();

#pragma unroll
        for (int kk = 0; kk < 8; kk++) {
            float ar[8], br[8];
            *(float4*)&ar[0] = *(const float4*)&As[kk][tr];
            *(float4*)&ar[4] = *(const float4*)&As[kk][tr + 4];
            *(float4*)&br[0] = *(const float4*)&Bs[kk][tc];
            *(float4*)&br[4] = *(const float4*)&Bs[kk][tc + 4];
#pragma unroll
            for (int i = 0; i < 8; i++)
#pragma unroll
                for (int j = 0; j < 8; j++)
                    acc[i][j] = fmaf(ar[i], br[j], acc[i][j]);
        }
        __syncthreads();
    }

    float bb[8];
#pragma unroll
    for (int j = 0; j < 8; j++) bb[j] = bias ? bias[colBlk + tc + j] : 0.f;

#pragma unroll
    for (int i = 0; i < 8; i++) {
        float* Cp = C + (long)(rowBlk + tr + i) * N + colBlk + tc;
        float4 o0, o1;
        o0.x = acc[i][0] + bb[0]; o0.y = acc[i][1] + bb[1];
        o0.z = acc[i][2] + bb[2]; o0.w = acc[i][3] + bb[3];
        o1.x = acc[i][4] + bb[4]; o1.y = acc[i][5] + bb[5];
        o1.z = acc[i][6] + bb[6]; o1.w = acc[i][7] + bb[7];
        *(float4*)Cp       = o0;
        *(float4*)(Cp + 4) = o1;
    }
}

// ---------------------------------------------------------------------------
// fp32 -> bf16 hi/lo split (elementwise, optional scale), float4-vectorized
// ---------------------------------------------------------------------------
__global__ __launch_bounds__(256) void split_kernel(
    const float* __restrict__ in, __nv_bfloat16* __restrict__ hi,
    __nv_bfloat16* __restrict__ lo, int n4, float scale)
{
    int i = blockIdx.x * 256 + threadIdx.x;
    if (i >= n4) return;
    float4 v = ((const float4*)in)[i];
    float f[4] = {v.x * scale, v.y * scale, v.z * scale, v.w * scale};
    __nv_bfloat162 H0, H1, L0, L1;
    H0.x = __float2bfloat16(f[0]); H0.y = __float2bfloat16(f[1]);
    H1.x = __float2bfloat16(f[2]); H1.y = __float2bfloat16(f[3]);
    L0.x = __float2bfloat16(f[0] - __bfloat162float(H0.x));
    L0.y = __float2bfloat16(f[1] - __bfloat162float(H0.y));
    L1.x = __float2bfloat16(f[2] - __bfloat162float(H1.x));
    L1.y = __float2bfloat16(f[3] - __bfloat162float(H1.y));
    uint2 uh, ul;
    uh.x = *(unsigned*)&H0; uh.y = *(unsigned*)&H1;
    ul.x = *(unsigned*)&L0; ul.y = *(unsigned*)&L1;
    ((uint2*)hi)[i] = uh;
    ((uint2*)lo)[i] = ul;
}

// ---------------------------------------------------------------------------
// V transpose + split: g_V[b][k][h*64+d] -> Vt[b][h][d][k] (bf16 hi/lo)
// 32x32 tiles via smem; coalesced on both sides.
// ---------------------------------------------------------------------------
__global__ __launch_bounds__(256) void vsplit_kernel(
    const float* __restrict__ V, __nv_bfloat16* __restrict__ vh,
    __nv_bfloat16* __restrict__ vl)
{
    __shared__ float tile[32][33];
    const int k0 = blockIdx.x * 32, d0 = blockIdx.y * 32, bh = blockIdx.z;
    const int b = bh >> 3, h = bh & 7;
    const float* src = V + (long)b * NKL * NIN + h * NDH;

    for (int yy = threadIdx.y; yy < 32; yy += 8)
        tile[yy][threadIdx.x] = src[(long)(k0 + yy) * NIN + d0 + threadIdx.x];
    __syncthreads();

    const long obase = (long)bh * NDH * NKL;
    for (int yy = threadIdx.y; yy < 32; yy += 8) {
        float x = tile[threadIdx.x][yy];
        long oidx = obase + (long)(d0 + yy) * NKL + k0 + threadIdx.x;
        __nv_bfloat16 hh = __float2bfloat16(x);
        vh[oidx] = hh;
        vl[oidx] = __float2bfloat16(x - __bfloat162float(hh));
    }
}

// ---------------------------------------------------------------------------
// bf16-split flash attention on mma.sync.m16n8k16 (HMMA)
// Block = 64 q of one (b,h); 4 warps, each warp a 16-q slab.
// S = Qh*Kh + Qh*Kl + Ql*Kh ; O += Ph*Vh + Ph*Vl + Pl*Vh (fp32 accumulate)
// Q fragments cached in registers across the whole key loop.
// P fragments built register-to-register from the S accumulator fragments.
// smem rows padded to 72 bf16 -> fragment LDS banks = (4g+t), conflict-free.
// ---------------------------------------------------------------------------
__device__ __forceinline__ void mma_bf16(float d[4], const unsigned a[4],
                                         unsigned b0, unsigned b1)
{
    asm volatile(
        "mma.sync.aligned.m16n8k16.row.col.f32.bf16.bf16.f32 "
        "{%0,%1,%2,%3}, {%4,%5,%6,%7}, {%8,%9}, {%0,%1,%2,%3};"
        : "+f"(d[0]), "+f"(d[1]), "+f"(d[2]), "+f"(d[3])
        : "r"(a[0]), "r"(a[1]), "r"(a[2]), "r"(a[3]), "r"(b0), "r"(b1));
}

__global__ __launch_bounds__(128) void attn_mma_kernel(
    const __nv_bfloat16* __restrict__ Qh, const __nv_bfloat16* __restrict__ Ql,
    const __nv_bfloat16* __restrict__ Kh, const __nv_bfloat16* __restrict__ Kl,
    const __nv_bfloat16* __restrict__ Vh, const __nv_bfloat16* __restrict__ Vl,
    float* __restrict__ O)
{
    __shared__ __nv_bfloat16 sKh[64][72];
    __shared__ __nv_bfloat16 sKl[64][72];
    __shared__ __nv_bfloat16 sVh[64][72];   // V transposed: [d][k]
    __shared__ __nv_bfloat16 sVl[64][72];

    const int tid  = threadIdx.x;
    const int lane = tid & 31;
    const int w    = tid >> 5;
    const int g    = lane >> 2;   // fragment group row
    const int t    = lane & 3;    // fragment thread-in-group

    const int qt = blockIdx.x, h = blockIdx.y, b = blockIdx.z;

    // ---- Q fragments in registers (constant across key loop) ----
    unsigned qfh[4][4], qfl[4][4];
    {
        const long qoff = ((long)(b * NQL + qt * 64 + w * 16)) * NIN + h * NDH;
        const __nv_bfloat16* qh = Qh + qoff;
        const __nv_bfloat16* ql = Ql + qoff;
#pragma unroll
        for (int j = 0; j < 4; j++) {
            int d0 = 16 * j + 2 * t;
            qfh[j][0] = *(const unsigned*)(qh + (long)g * NIN + d0);
            qfh[j][1] = *(const unsigned*)(qh + (long)(g + 8) * NIN + d0);
            qfh[j][2] = *(const unsigned*)(qh + (long)g * NIN + d0 + 8);
            qfh[j][3] = *(const unsigned*)(qh + (long)(g + 8) * NIN + d0 + 8);
            qfl[j][0] = *(const unsigned*)(ql + (long)g * NIN + d0);
            qfl[j][1] = *(const unsigned*)(ql + (long)(g + 8) * NIN + d0);
            qfl[j][2] = *(const unsigned*)(ql + (long)g * NIN + d0 + 8);
            qfl[j][3] = *(const unsigned*)(ql + (long)(g + 8) * NIN + d0 + 8);
        }
    }

    float o[8][4];
#pragma unroll
    for (int ct = 0; ct < 8; ct++)
#pragma unroll
        for (int e = 0; e < 4; e++) o[ct][e] = 0.f;
    float m0 = -1e30f, m1 = -1e30f, l0 = 0.f, l1 = 0.f;

    const __nv_bfloat16* kbh = Kh + (long)b * NKL * NIN + h * NDH;
    const __nv_bfloat16* kbl = Kl + (long)b * NKL * NIN + h * NDH;
    const __nv_bfloat16* vbh = Vh + (long)(b * NH + h) * NDH * NKL;
    const __nv_bfloat16* vbl = Vl + (long)(b * NH + h) * NDH * NKL;

    for (int kt = 0; kt < NKL / 64; kt++) {
        __syncthreads();   // previous tile's consumers done
        // ---- load K / Vt tiles (16B chunks, coalesced) ----
#pragma unroll
        for (int i = 0; i < 4; i++) {
            int c  = tid + 128 * i;
            int r  = c >> 3, c8 = c & 7;
            long koff = (long)(kt * 64 + r) * NIN + c8 * 8;
            long voff = (long)r * NKL + kt * 64 + c8 * 8;
            *(uint4*)&sKh[r][c8 * 8] = *(const uint4*)(kbh + koff);
            *(uint4*)&sKl[r][c8 * 8] = *(const uint4*)(kbl + koff);
            *(uint4*)&sVh[r][c8 * 8] = *(const uint4*)(vbh + voff);
            *(uint4*)&sVl[r][c8 * 8] = *(const uint4*)(vbl + voff);
        }
        __syncthreads();

        // ---- S = Q @ K^T (bf16x3) ----
        float s[8][4];
#pragma unroll
        for (int nt = 0; nt < 8; nt++) {
            s[nt][0] = s[nt][1] = s[nt][2] = s[nt][3] = 0.f;
#pragma unroll
            for (int j = 0; j < 4; j++) {
                int row = 8 * nt + g, col = 16 * j + 2 * t;
                unsigned bh0 = *(const unsigned*)&sKh[row][col];
                unsigned bh1 = *(const unsigned*)&sKh[row][col + 8];
                unsigned bl0 = *(const unsigned*)&sKl[row][col];
                unsigned bl1 = *(const unsigned*)&sKl[row][col + 8];
                mma_bf16(s[nt], qfh[j], bh0, bh1);
                mma_bf16(s[nt], qfh[j], bl0, bl1);
                mma_bf16(s[nt], qfl[j], bh0, bh1);
            }
        }

        // ---- online softmax (rows g and g+8; reduce over 4 t-lanes) ----
        float mt0 = -1e30f, mt1 = -1e30f;
#pragma unroll
        for (int nt = 0; nt < 8; nt++) {
            mt0 = fmaxf(mt0, fmaxf(s[nt][0], s[nt][1]));
            mt1 = fmaxf(mt1, fmaxf(s[nt][2], s[nt][3]));
        }
        mt0 = fmaxf(mt0, __shfl_xor_sync(0xffffffffu, mt0, 1));
        mt0 = fmaxf(mt0, __shfl_xor_sync(0xffffffffu, mt0, 2));
        mt1 = fmaxf(mt1, __shfl_xor_sync(0xffffffffu, mt1, 1));
        mt1 = fmaxf(mt1, __shfl_xor_sync(0xffffffffu, mt1, 2));
        float mn0 = fmaxf(m0, mt0), mn1 = fmaxf(m1, mt1);
        float cr0 = __expf(m0 - mn0), cr1 = __expf(m1 - mn1);
        m0 = mn0; m1 = mn1;

        float rs0 = 0.f, rs1 = 0.f;
        unsigned ph[8][2], pl[8][2];
#pragma unroll
        for (int nt = 0; nt < 8; nt++) {
            float p0 = __expf(s[nt][0] - m0), p1 = __expf(s[nt][1] - m0);
            float p2 = __expf(s[nt][2] - m1), p3 = __expf(s[nt][3] - m1);
            rs0 += p0 + p1; rs1 += p2 + p3;
            __nv_bfloat162 H, L;
            H.x = __float2bfloat16(p0); H.y = __float2bfloat16(p1);
            L.x = __float2bfloat16(p0 - __bfloat162float(H.x));
            L.y = __float2bfloat16(p1 - __bfloat162float(H.y));
            ph[nt][0] = *(unsigned*)&H; pl[nt][0] = *(unsigned*)&L;
            H.x = __float2bfloat16(p2); H.y = __float2bfloat16(p3);
            L.x = __float2bfloat16(p2 - __bfloat162float(H.x));
            L.y = __float2bfloat16(p3 - __bfloat162float(H.y));
            ph[nt][1] = *(unsigned*)&H; pl[nt][1] = *(unsigned*)&L;
        }
        rs0 += __shfl_xor_sync(0xffffffffu, rs0, 1);
        rs0 += __shfl_xor_sync(0xffffffffu, rs0, 2);
        rs1 += __shfl_xor_sync(0xffffffffu, rs1, 1);
        rs1 += __shfl_xor_sync(0xffffffffu, rs1, 2);
        l0 = l0 * cr0 + rs0;
        l1 = l1 * cr1 + rs1;
#pragma unroll
        for (int ct = 0; ct < 8; ct++) {
            o[ct][0] *= cr0; o[ct][1] *= cr0;
            o[ct][2] *= cr1; o[ct][3] *= cr1;
        }

        // ---- O += P @ V (bf16x3); P A-frags direct from S frags ----
#pragma unroll
        for (int j = 0; j < 4; j++) {
            unsigned ah[4] = {ph[2 * j][0], ph[2 * j][1],
                              ph[2 * j + 1][0], ph[2 * j + 1][1]};
            unsigned al[4] = {pl[2 * j][0], pl[2 * j][1],
                              pl[2 * j + 1][0], pl[2 * j + 1][1]};
#pragma unroll
            for (int ct = 0; ct < 8; ct++) {
                int row = 8 * ct + g, col = 16 * j + 2 * t;
                unsigned vh0 = *(const unsigned*)&sVh[row][col];
                unsigned vh1 = *(const unsigned*)&sVh[row][col + 8];
                unsigned vl0 = *(const unsigned*)&sVl[row][col];
                unsigned vl1 = *(const unsigned*)&sVl[row][col + 8];
                mma_bf16(o[ct], ah, vh0, vh1);
                mma_bf16(o[ct], ah, vl0, vl1);
                mma_bf16(o[ct], al, vh0, vh1);
            }
        }
    }

    // ---- epilogue: normalize, write g_O[b][q][h*64 + c] ----
    float i0 = 1.f / l0, i1 = 1.f / l1;
    float* op = O + ((long)(b * NQL + qt * 64 + w * 16)) * NIN + h * NDH;
#pragma unroll
    for (int ct = 0; ct < 8; ct++) {
        int cc = 8 * ct + 2 * t;
        float2 w0, w1;
        w0.x = o[ct][0] * i0; w0.y = o[ct][1] * i0;
        w1.x = o[ct][2] * i1; w1.y = o[ct][3] * i1;
        *(float2*)(op + (long)g * NIN + cc)       = w0;
        *(float2*)(op + (long)(g + 8) * NIN + cc) = w1;
    }
}

// ---------------------------------------------------------------------------
// Launch pipeline (graph-capturable: kernel launches only)
// ---------------------------------------------------------------------------
extern "C" void kernel_launch(void* const* d_in, const int* in_sizes, int n_in,
                              void* d_out, int out_size)
{
    (void)in_sizes; (void)n_in; (void)out_size;
    const float* x   = (const float*)d_in[0];
    const float* ctx = (const float*)d_in[1];
    const float* Wq  = (const float*)d_in[2];
    const float* Wk  = (const float*)d_in[3];
    const float* Wv  = (const float*)d_in[4];
    const float* Wo  = (const float*)d_in[5];
    const float* bo  = (const float*)d_in[6];
    float* out = (float*)d_out;

    float *Qf, *Kf, *Vf, *Of;
    __nv_bfloat16 *Qh, *Ql, *Kh, *Kl, *Vh, *Vl;
    cudaGetSymbolAddress((void**)&Qf, g_Q);
    cudaGetSymbolAddress((void**)&Kf, g_K);
    cudaGetSymbolAddress((void**)&Vf, g_V);
    cudaGetSymbolAddress((void**)&Of, g_O);
    cudaGetSymbolAddress((void**)&Qh, g_Qh);
    cudaGetSymbolAddress((void**)&Ql, g_Ql);
    cudaGetSymbolAddress((void**)&Kh, g_Kh);
    cudaGetSymbolAddress((void**)&Kl, g_Kl);
    cudaGetSymbolAddress((void**)&Vh, g_Vh);
    cudaGetSymbolAddress((void**)&Vl, g_Vl);

    // Projections (FFMA SGEMM)
    dim3 gq(NIN / 128, (NB * NQL) / 128);
    sgemm_kernel<<<gq, 256>>>(x,   Wq, nullptr, Qf, NB * NQL, NIN, NQD);
    dim3 gk(NIN / 128, (NB * NKL) / 128);
    sgemm_kernel<<<gk, 256>>>(ctx, Wk, nullptr, Kf, NB * NKL, NIN, NCD);
    sgemm_kernel<<<gk, 256>>>(ctx, Wv, nullptr, Vf, NB * NKL, NIN, NCD);

    // bf16 hi/lo splits (Q pre-scaled by DH^-0.5), V transposed per head
    const int n4 = NELEM / 4;
    split_kernel<<<(n4 + 255) / 256, 256>>>(Qf, Qh, Ql, n4, ATTN_SCALE);
    split_kernel<<<(n4 + 255) / 256, 256>>>(Kf, Kh, Kl, n4, 1.0f);
    dim3 gv(NKL / 32, NDH / 32, NB * NH);
    vsplit_kernel<<<gv, dim3(32, 8)>>>(Vf, Vh, Vl);

    // Flash attention on tensor cores
    dim3 ga(NQL / 64, NH, NB);
    attn_mma_kernel<<<ga, 128>>>(Qh, Ql, Kh, Kl, Vh, Vl, Of);

    // Output projection with bias
    dim3 go(NQD / 128, (NB * NQL) / 128);
    sgemm_kernel<<<go, 256>>>(Of, Wo, bo, out, NB * NQL, NQD, NIN);
}

// round 12
// speedup vs baseline: 2.5454x; 1.0014x over previous
#include <cuda_runtime.h>
#include <cuda_bf16.h>

// Problem constants (fixed shapes)
#define NB   2
#define NQL  4096
#define NKL  4096
#define NQD  512
#define NCD  768
#define NH   8
#define NDH  64
#define NIN  512            // H * DH
#define ATTN_SCALE 0.125f   // DH^-0.5

#define NELEM (NB * NQL * NIN)   // 8M elements (QL == KL here)

// Scratch (static device globals -- allocation-free per harness rules)
__device__ float g_Q[NELEM];
__device__ float g_K[NELEM];
__device__ float g_V[NELEM];
__device__ float g_O[NELEM];
__device__ __nv_bfloat16 g_Qh[NELEM];
__device__ __nv_bfloat16 g_Ql[NELEM];
__device__ __nv_bfloat16 g_Kh[NELEM];
__device__ __nv_bfloat16 g_Kl[NELEM];
__device__ __nv_bfloat16 g_Vh[NELEM];   // transposed: [b][h][d][k]
__device__ __nv_bfloat16 g_Vl[NELEM];

// ---------------------------------------------------------------------------
// Tiled FFMA SGEMM (unchanged from R9): C[M,N] = A[M,K] @ B[K,N] (+ bias)
// ---------------------------------------------------------------------------
__global__ __launch_bounds__(256) void sgemm_kernel(
    const float* __restrict__ A, const float* __restrict__ Bm,
    const float* __restrict__ bias, float* __restrict__ C,
    int M, int N, int K)
{
    __shared__ float As[8][128];
    __shared__ float Bs[8][128];

    const int tid    = threadIdx.x;
    const int rowBlk = blockIdx.y << 7;
    const int colBlk = blockIdx.x << 7;

    const int aRow = tid >> 1;
    const int aCol = (tid & 1) << 2;
    const int bRow = tid >> 5;
    const int bCol = (tid & 31) << 2;

    const int tr = (tid >> 4) << 3;
    const int tc = (tid & 15) << 3;

    float acc[8][8];
#pragma unroll
    for (int i = 0; i < 8; i++)
#pragma unroll
        for (int j = 0; j < 8; j++) acc[i][j] = 0.f;

    const float* Ap = A + (long)(rowBlk + aRow) * K + aCol;
    const float* Bp = Bm + (long)bRow * N + colBlk + bCol;

    for (int k0 = 0; k0 < K; k0 += 8) {
        float4 av = *(const float4*)(Ap + k0);
        As[aCol + 0][aRow] = av.x;
        As[aCol + 1][aRow] = av.y;
        As[aCol + 2][aRow] = av.z;
        As[aCol + 3][aRow] = av.w;
        *(float4*)&Bs[bRow][bCol] = *(const float4*)(Bp + (long)k0 * N);
        __syncthreads();

#pragma unroll
        for (int kk = 0; kk < 8; kk++) {
            float ar[8], br[8];
            *(float4*)&ar[0] = *(const float4*)&As[kk][tr];
            *(float4*)&ar[4] = *(const float4*)&As[kk][tr + 4];
            *(float4*)&br[0] = *(const float4*)&Bs[kk][tc];
            *(float4*)&br[4] = *(const float4*)&Bs[kk][tc + 4];
#pragma unroll
            for (int i = 0; i < 8; i++)
#pragma unroll
                for (int j = 0; j < 8; j++)
                    acc[i][j] = fmaf(ar[i], br[j], acc[i][j]);
        }
        __syncthreads();
    }

    float bb[8];
#pragma unroll
    for (int j = 0; j < 8; j++) bb[j] = bias ? bias[colBlk + tc + j] : 0.f;

#pragma unroll
    for (int i = 0; i < 8; i++) {
        float* Cp = C + (long)(rowBlk + tr + i) * N + colBlk + tc;
        float4 o0, o1;
        o0.x = acc[i][0] + bb[0]; o0.y = acc[i][1] + bb[1];
        o0.z = acc[i][2] + bb[2]; o0.w = acc[i][3] + bb[3];
        o1.x = acc[i][4] + bb[4]; o1.y = acc[i][5] + bb[5];
        o1.z = acc[i][6] + bb[6]; o1.w = acc[i][7] + bb[7];
        *(float4*)Cp       = o0;
        *(float4*)(Cp + 4) = o1;
    }
}

// ---------------------------------------------------------------------------
// fp32 -> bf16 hi/lo split (elementwise, optional scale), float4-vectorized
// ---------------------------------------------------------------------------
__global__ __launch_bounds__(256) void split_kernel(
    const float* __restrict__ in, __nv_bfloat16* __restrict__ hi,
    __nv_bfloat16* __restrict__ lo, int n4, float scale)
{
    int i = blockIdx.x * 256 + threadIdx.x;
    if (i >= n4) return;
    float4 v = ((const float4*)in)[i];
    float f[4] = {v.x * scale, v.y * scale, v.z * scale, v.w * scale};
    __nv_bfloat162 H0, H1, L0, L1;
    H0.x = __float2bfloat16(f[0]); H0.y = __float2bfloat16(f[1]);
    H1.x = __float2bfloat16(f[2]); H1.y = __float2bfloat16(f[3]);
    L0.x = __float2bfloat16(f[0] - __bfloat162float(H0.x));
    L0.y = __float2bfloat16(f[1] - __bfloat162float(H0.y));
    L1.x = __float2bfloat16(f[2] - __bfloat162float(H1.x));
    L1.y = __float2bfloat16(f[3] - __bfloat162float(H1.y));
    uint2 uh, ul;
    uh.x = *(unsigned*)&H0; uh.y = *(unsigned*)&H1;
    ul.x = *(unsigned*)&L0; ul.y = *(unsigned*)&L1;
    ((uint2*)hi)[i] = uh;
    ((uint2*)lo)[i] = ul;
}

// ---------------------------------------------------------------------------
// V transpose + split: g_V[b][k][h*64+d] -> Vt[b][h][d][k] (bf16 hi/lo)
// 32x32 tiles via smem; coalesced on both sides.
// ---------------------------------------------------------------------------
__global__ __launch_bounds__(256) void vsplit_kernel(
    const float* __restrict__ V, __nv_bfloat16* __restrict__ vh,
    __nv_bfloat16* __restrict__ vl)
{
    __shared__ float tile[32][33];
    const int k0 = blockIdx.x * 32, d0 = blockIdx.y * 32, bh = blockIdx.z;
    const int b = bh >> 3, h = bh & 7;
    const float* src = V + (long)b * NKL * NIN + h * NDH;

    for (int yy = threadIdx.y; yy < 32; yy += 8)
        tile[yy][threadIdx.x] = src[(long)(k0 + yy) * NIN + d0 + threadIdx.x];
    __syncthreads();

    const long obase = (long)bh * NDH * NKL;
    for (int yy = threadIdx.y; yy < 32; yy += 8) {
        float x = tile[threadIdx.x][yy];
        long oidx = obase + (long)(d0 + yy) * NKL + k0 + threadIdx.x;
        __nv_bfloat16 hh = __float2bfloat16(x);
        vh[oidx] = hh;
        vl[oidx] = __float2bfloat16(x - __bfloat162float(hh));
    }
}

// ---------------------------------------------------------------------------
// bf16-split flash attention on mma.sync.m16n8k16 (HMMA)
// Block = 64 q of one (b,h); 4 warps, each warp a 16-q slab.
// S = Qh*Kh + Qh*Kl + Ql*Kh ; O += Ph*Vh + Ph*Vl + Pl*Vh (fp32 accumulate)
// Q fragments cached in registers across the whole key loop.
// P fragments built register-to-register from the S accumulator fragments.
// smem rows padded to 72 bf16 -> fragment LDS banks = (4g+t), conflict-free.
// ---------------------------------------------------------------------------
__device__ __forceinline__ void mma_bf16(float d[4], const unsigned a[4],
                                         unsigned b0, unsigned b1)
{
    asm volatile(
        "mma.sync.aligned.m16n8k16.row.col.f32.bf16.bf16.f32 "
        "{%0,%1,%2,%3}, {%4,%5,%6,%7}, {%8,%9}, {%0,%1,%2,%3};"
        : "+f"(d[0]), "+f"(d[1]), "+f"(d[2]), "+f"(d[3])
        : "r"(a[0]), "r"(a[1]), "r"(a[2]), "r"(a[3]), "r"(b0), "r"(b1));
}

__global__ __launch_bounds__(128) void attn_mma_kernel(
    const __nv_bfloat16* __restrict__ Qh, const __nv_bfloat16* __restrict__ Ql,
    const __nv_bfloat16* __restrict__ Kh, const __nv_bfloat16* __restrict__ Kl,
    const __nv_bfloat16* __restrict__ Vh, const __nv_bfloat16* __restrict__ Vl,
    float* __restrict__ O)
{
    __shared__ __nv_bfloat16 sKh[64][72];
    __shared__ __nv_bfloat16 sKl[64][72];
    __shared__ __nv_bfloat16 sVh[64][72];   // V transposed: [d][k]
    __shared__ __nv_bfloat16 sVl[64][72];

    const int tid  = threadIdx.x;
    const int lane = tid & 31;
    const int w    = tid >> 5;
    const int g    = lane >> 2;   // fragment group row
    const int t    = lane & 3;    // fragment thread-in-group

    const int qt = blockIdx.x, h = blockIdx.y, b = blockIdx.z;

    // ---- Q fragments in registers (constant across key loop) ----
    unsigned qfh[4][4], qfl[4][4];
    {
        const long qoff = ((long)(b * NQL + qt * 64 + w * 16)) * NIN + h * NDH;
        const __nv_bfloat16* qh = Qh + qoff;
        const __nv_bfloat16* ql = Ql + qoff;
#pragma unroll
        for (int j = 0; j < 4; j++) {
            int d0 = 16 * j + 2 * t;
            qfh[j][0] = *(const unsigned*)(qh + (long)g * NIN + d0);
            qfh[j][1] = *(const unsigned*)(qh + (long)(g + 8) * NIN + d0);
            qfh[j][2] = *(const unsigned*)(qh + (long)g * NIN + d0 + 8);
            qfh[j][3] = *(const unsigned*)(qh + (long)(g + 8) * NIN + d0 + 8);
            qfl[j][0] = *(const unsigned*)(ql + (long)g * NIN + d0);
            qfl[j][1] = *(const unsigned*)(ql + (long)(g + 8) * NIN + d0);
            qfl[j][2] = *(const unsigned*)(ql + (long)g * NIN + d0 + 8);
            qfl[j][3] = *(const unsigned*)(ql + (long)(g + 8) * NIN + d0 + 8);
        }
    }

    float o[8][4];
#pragma unroll
    for (int ct = 0; ct < 8; ct++)
#pragma unroll
        for (int e = 0; e < 4; e++) o[ct][e] = 0.f;
    float m0 = -1e30f, m1 = -1e30f, l0 = 0.f, l1 = 0.f;

    const __nv_bfloat16* kbh = Kh + (long)b * NKL * NIN + h * NDH;
    const __nv_bfloat16* kbl = Kl + (long)b * NKL * NIN + h * NDH;
    const __nv_bfloat16* vbh = Vh + (long)(b * NH + h) * NDH * NKL;
    const __nv_bfloat16* vbl = Vl + (long)(b * NH + h) * NDH * NKL;

    for (int kt = 0; kt < NKL / 64; kt++) {
        __syncthreads();   // previous tile's consumers done
        // ---- load K / Vt tiles (16B chunks, coalesced) ----
#pragma unroll
        for (int i = 0; i < 4; i++) {
            int c  = tid + 128 * i;
            int r  = c >> 3, c8 = c & 7;
            long koff = (long)(kt * 64 + r) * NIN + c8 * 8;
            long voff = (long)r * NKL + kt * 64 + c8 * 8;
            *(uint4*)&sKh[r][c8 * 8] = *(const uint4*)(kbh + koff);
            *(uint4*)&sKl[r][c8 * 8] = *(const uint4*)(kbl + koff);
            *(uint4*)&sVh[r][c8 * 8] = *(const uint4*)(vbh + voff);
            *(uint4*)&sVl[r][c8 * 8] = *(const uint4*)(vbl + voff);
        }
        __syncthreads();

        // ---- S = Q @ K^T (bf16x3) ----
        float s[8][4];
#pragma unroll
        for (int nt = 0; nt < 8; nt++) {
            s[nt][0] = s[nt][1] = s[nt][2] = s[nt][3] = 0.f;
#pragma unroll
            for (int j = 0; j < 4; j++) {
                int row = 8 * nt + g, col = 16 * j + 2 * t;
                unsigned bh0 = *(const unsigned*)&sKh[row][col];
                unsigned bh1 = *(const unsigned*)&sKh[row][col + 8];
                unsigned bl0 = *(const unsigned*)&sKl[row][col];
                unsigned bl1 = *(const unsigned*)&sKl[row][col + 8];
                mma_bf16(s[nt], qfh[j], bh0, bh1);
                mma_bf16(s[nt], qfh[j], bl0, bl1);
                mma_bf16(s[nt], qfl[j], bh0, bh1);
            }
        }

        // ---- online softmax (rows g and g+8; reduce over 4 t-lanes) ----
        float mt0 = -1e30f, mt1 = -1e30f;
#pragma unroll
        for (int nt = 0; nt < 8; nt++) {
            mt0 = fmaxf(mt0, fmaxf(s[nt][0], s[nt][1]));
            mt1 = fmaxf(mt1, fmaxf(s[nt][2], s[nt][3]));
        }
        mt0 = fmaxf(mt0, __shfl_xor_sync(0xffffffffu, mt0, 1));
        mt0 = fmaxf(mt0, __shfl_xor_sync(0xffffffffu, mt0, 2));
        mt1 = fmaxf(mt1, __shfl_xor_sync(0xffffffffu, mt1, 1));
        mt1 = fmaxf(mt1, __shfl_xor_sync(0xffffffffu, mt1, 2));
        float mn0 = fmaxf(m0, mt0), mn1 = fmaxf(m1, mt1);
        float cr0 = __expf(m0 - mn0), cr1 = __expf(m1 - mn1);
        m0 = mn0; m1 = mn1;

        float rs0 = 0.f, rs1 = 0.f;
        unsigned ph[8][2], pl[8][2];
#pragma unroll
        for (int nt = 0; nt < 8; nt++) {
            float p0 = __expf(s[nt][0] - m0), p1 = __expf(s[nt][1] - m0);
            float p2 = __expf(s[nt][2] - m1), p3 = __expf(s[nt][3] - m1);
            rs0 += p0 + p1; rs1 += p2 + p3;
            __nv_bfloat162 H, L;
            H.x = __float2bfloat16(p0); H.y = __float2bfloat16(p1);
            L.x = __float2bfloat16(p0 - __bfloat162float(H.x));
            L.y = __float2bfloat16(p1 - __bfloat162float(H.y));
            ph[nt][0] = *(unsigned*)&H; pl[nt][0] = *(unsigned*)&L;
            H.x = __float2bfloat16(p2); H.y = __float2bfloat16(p3);
            L.x = __float2bfloat16(p2 - __bfloat162float(H.x));
            L.y = __float2bfloat16(p3 - __bfloat162float(H.y));
            ph[nt][1] = *(unsigned*)&H; pl[nt][1] = *(unsigned*)&L;
        }
        rs0 += __shfl_xor_sync(0xffffffffu, rs0, 1);
        rs0 += __shfl_xor_sync(0xffffffffu, rs0, 2);
        rs1 += __shfl_xor_sync(0xffffffffu, rs1, 1);
        rs1 += __shfl_xor_sync(0xffffffffu, rs1, 2);
        l0 = l0 * cr0 + rs0;
        l1 = l1 * cr1 + rs1;
#pragma unroll
        for (int ct = 0; ct < 8; ct++) {
            o[ct][0] *= cr0; o[ct][1] *= cr0;
            o[ct][2] *= cr1; o[ct][3] *= cr1;
        }

        // ---- O += P @ V (bf16x3); P A-frags direct from S frags ----
#pragma unroll
        for (int j = 0; j < 4; j++) {
            unsigned ah[4] = {ph[2 * j][0], ph[2 * j][1],
                              ph[2 * j + 1][0], ph[2 * j + 1][1]};
            unsigned al[4] = {pl[2 * j][0], pl[2 * j][1],
                              pl[2 * j + 1][0], pl[2 * j + 1][1]};
#pragma unroll
            for (int ct = 0; ct < 8; ct++) {
                int row = 8 * ct + g, col = 16 * j + 2 * t;
                unsigned vh0 = *(const unsigned*)&sVh[row][col];
                unsigned vh1 = *(const unsigned*)&sVh[row][col + 8];
                unsigned vl0 = *(const unsigned*)&sVl[row][col];
                unsigned vl1 = *(const unsigned*)&sVl[row][col + 8];
                mma_bf16(o[ct], ah, vh0, vh1);
                mma_bf16(o[ct], ah, vl0, vl1);
                mma_bf16(o[ct], al, vh0, vh1);
            }
        }
    }

    // ---- epilogue: normalize, write g_O[b][q][h*64 + c] ----
    float i0 = 1.f / l0, i1 = 1.f / l1;
    float* op = O + ((long)(b * NQL + qt * 64 + w * 16)) * NIN + h * NDH;
#pragma unroll
    for (int ct = 0; ct < 8; ct++) {
        int cc = 8 * ct + 2 * t;
        float2 w0, w1;
        w0.x = o[ct][0] * i0; w0.y = o[ct][1] * i0;
        w1.x = o[ct][2] * i1; w1.y = o[ct][3] * i1;
        *(float2*)(op + (long)g * NIN + cc)       = w0;
        *(float2*)(op + (long)(g + 8) * NIN + cc) = w1;
    }
}

// ---------------------------------------------------------------------------
// Launch pipeline (graph-capturable: kernel launches only)
// ---------------------------------------------------------------------------
extern "C" void kernel_launch(void* const* d_in, const int* in_sizes, int n_in,
                              void* d_out, int out_size)
{
    (void)in_sizes; (void)n_in; (void)out_size;
    const float* x   = (const float*)d_in[0];
    const float* ctx = (const float*)d_in[1];
    const float* Wq  = (const float*)d_in[2];
    const float* Wk  = (const float*)d_in[3];
    const float* Wv  = (const float*)d_in[4];
    const float* Wo  = (const float*)d_in[5];
    const float* bo  = (const float*)d_in[6];
    float* out = (float*)d_out;

    float *Qf, *Kf, *Vf, *Of;
    __nv_bfloat16 *Qh, *Ql, *Kh, *Kl, *Vh, *Vl;
    cudaGetSymbolAddress((void**)&Qf, g_Q);
    cudaGetSymbolAddress((void**)&Kf, g_K);
    cudaGetSymbolAddress((void**)&Vf, g_V);
    cudaGetSymbolAddress((void**)&Of, g_O);
    cudaGetSymbolAddress((void**)&Qh, g_Qh);
    cudaGetSymbolAddress((void**)&Ql, g_Ql);
    cudaGetSymbolAddress((void**)&Kh, g_Kh);
    cudaGetSymbolAddress((void**)&Kl, g_Kl);
    cudaGetSymbolAddress((void**)&Vh, g_Vh);
    cudaGetSymbolAddress((void**)&Vl, g_Vl);

    // Projections (FFMA SGEMM)
    dim3 gq(NIN / 128, (NB * NQL) / 128);
    sgemm_kernel<<<gq, 256>>>(x,   Wq, nullptr, Qf, NB * NQL, NIN, NQD);
    dim3 gk(NIN / 128, (NB * NKL) / 128);
    sgemm_kernel<<<gk, 256>>>(ctx, Wk, nullptr, Kf, NB * NKL, NIN, NCD);
    sgemm_kernel<<<gk, 256>>>(ctx, Wv, nullptr, Vf, NB * NKL, NIN, NCD);

    // bf16 hi/lo splits (Q pre-scaled by DH^-0.5), V transposed per head
    const int n4 = NELEM / 4;
    split_kernel<<<(n4 + 255) / 256, 256>>>(Qf, Qh, Ql, n4, ATTN_SCALE);
    split_kernel<<<(n4 + 255) / 256, 256>>>(Kf, Kh, Kl, n4, 1.0f);
    dim3 gv(NKL / 32, NDH / 32, NB * NH);
    vsplit_kernel<<<gv, dim3(32, 8)>>>(Vf, Vh, Vl);

    // Flash attention on tensor cores
    dim3 ga(NQL / 64, NH, NB);
    attn_mma_kernel<<<ga, 128>>>(Qh, Ql, Kh, Kl, Vh, Vl, Of);

    // Output projection with bias
    dim3 go(NQD / 128, (NB * NQL) / 128);
    sgemm_kernel<<<go, 256>>>(Of, Wo, bo, out, NB * NQL, NQD, NIN);
}

// round 13
// speedup vs baseline: 2.9963x; 1.1771x over previous
#include <cuda_runtime.h>
#include <cuda_bf16.h>

// Problem constants (fixed shapes)
#define NB   2
#define NQL  4096
#define NKL  4096
#define NQD  512
#define NCD  768
#define NH   8
#define NDH  64
#define NIN  512            // H * DH
#define ATTN_SCALE 0.125f   // DH^-0.5

// Scratch (static device globals -- allocation-free per harness rules)
__device__ __nv_bfloat16 g_Xh[NB * NQL * NQD];
__device__ __nv_bfloat16 g_Xl[NB * NQL * NQD];
__device__ __nv_bfloat16 g_Ch[NB * NKL * NCD];
__device__ __nv_bfloat16 g_Cl[NB * NKL * NCD];
__device__ __nv_bfloat16 g_Qh[NB * NQL * NIN];
__device__ __nv_bfloat16 g_Ql[NB * NQL * NIN];
__device__ __nv_bfloat16 g_Kh[NB * NKL * NIN];
__device__ __nv_bfloat16 g_Kl[NB * NKL * NIN];
__device__ __nv_bfloat16 g_Vh[NB * NKL * NIN];   // transposed: [b][h][d][k]
__device__ __nv_bfloat16 g_Vl[NB * NKL * NIN];
__device__ __nv_bfloat16 g_Oh[NB * NQL * NIN];
__device__ __nv_bfloat16 g_Ol[NB * NQL * NIN];
__device__ __nv_bfloat16 g_Wqh[NQD * NIN];       // all weights transposed: [N][K]
__device__ __nv_bfloat16 g_Wql[NQD * NIN];
__device__ __nv_bfloat16 g_Wkh[NCD * NIN];
__device__ __nv_bfloat16 g_Wkl[NCD * NIN];
__device__ __nv_bfloat16 g_Wvh[NCD * NIN];
__device__ __nv_bfloat16 g_Wvl[NCD * NIN];
__device__ __nv_bfloat16 g_Woh[NIN * NQD];
__device__ __nv_bfloat16 g_Wol[NIN * NQD];

// ---------------------------------------------------------------------------
// bf16 m16n8k16 MMA (fp32 accumulate)
// ---------------------------------------------------------------------------
__device__ __forceinline__ void mma_bf16(float d[4], const unsigned a[4],
                                         unsigned b0, unsigned b1)
{
    asm volatile(
        "mma.sync.aligned.m16n8k16.row.col.f32.bf16.bf16.f32 "
        "{%0,%1,%2,%3}, {%4,%5,%6,%7}, {%8,%9}, {%0,%1,%2,%3};"
        : "+f"(d[0]), "+f"(d[1]), "+f"(d[2]), "+f"(d[3])
        : "r"(a[0]), "r"(a[1]), "r"(a[2]), "r"(a[3]), "r"(b0), "r"(b1));
}

__device__ __forceinline__ void split1(float v, __nv_bfloat16& h, __nv_bfloat16& l)
{
    h = __float2bfloat16(v);
    l = __float2bfloat16(v - __bfloat162float(h));
}

// ---------------------------------------------------------------------------
// fp32 -> bf16 hi/lo split (elementwise), float4-vectorized
// ---------------------------------------------------------------------------
__global__ __launch_bounds__(256) void split_kernel(
    const float* __restrict__ in, __nv_bfloat16* __restrict__ hi,
    __nv_bfloat16* __restrict__ lo, int n4)
{
    int i = blockIdx.x * 256 + threadIdx.x;
    if (i >= n4) return;
    float4 v = ((const float4*)in)[i];
    float f[4] = {v.x, v.y, v.z, v.w};
    __nv_bfloat162 H0, H1, L0, L1;
    split1(f[0], H0.x, L0.x); split1(f[1], H0.y, L0.y);
    split1(f[2], H1.x, L1.x); split1(f[3], H1.y, L1.y);
    uint2 uh, ul;
    uh.x = *(unsigned*)&H0; uh.y = *(unsigned*)&H1;
    ul.x = *(unsigned*)&L0; ul.y = *(unsigned*)&L1;
    ((uint2*)hi)[i] = uh;
    ((uint2*)lo)[i] = ul;
}

// ---------------------------------------------------------------------------
// Weight transpose + split: W[K][N] fp32 -> Wt[N][K] bf16 hi/lo
// ---------------------------------------------------------------------------
__global__ __launch_bounds__(256) void wsplit_kernel(
    const float* __restrict__ W, __nv_bfloat16* __restrict__ wh,
    __nv_bfloat16* __restrict__ wl, int K, int N)
{
    __shared__ float tile[32][33];
    const int k0 = blockIdx.x * 32, n0 = blockIdx.y * 32;
    for (int yy = threadIdx.y; yy < 32; yy += 8)
        tile[yy][threadIdx.x] = W[(long)(k0 + yy) * N + n0 + threadIdx.x];
    __syncthreads();
    for (int yy = threadIdx.y; yy < 32; yy += 8) {
        float x = tile[threadIdx.x][yy];      // = W[k0+tx][n0+yy]
        long o = (long)(n0 + yy) * K + k0 + threadIdx.x;
        __nv_bfloat16 hh, ll;
        split1(x, hh, ll);
        wh[o] = hh; wl[o] = ll;
    }
}

// ---------------------------------------------------------------------------
// bf16x3 GEMM on mma.sync: C[M,N] = (Ah+Al)[M,K] @ (Bh+Bl)[N,K]^T
// Block: 128x128 tile, BK=32, 256 threads = 8 warps (4 m-slabs x 2 n-slabs),
// each warp 32m x 64n = 2 m16 x 8 n8 fragments. Rows padded to 40 bf16
// (word pitch 20 -> fragment LDS banks 20g+t+4s cover all 32 banks).
// MODE 0: Cf = acc + bias (fp32).
// MODE 1: Ch/Cl = bf16 hi/lo split of acc*scale (same [M][N] layout).
// MODE 2: V-transposed split: acc at (token row, inner col) -> [b][h][d][k].
// ---------------------------------------------------------------------------
template <int MODE>
__global__ __launch_bounds__(256) void gemm3_kernel(
    const __nv_bfloat16* __restrict__ Ah, const __nv_bfloat16* __restrict__ Al,
    const __nv_bfloat16* __restrict__ Bh, const __nv_bfloat16* __restrict__ Bl,
    const float* __restrict__ bias, float* __restrict__ Cf,
    __nv_bfloat16* __restrict__ Ch, __nv_bfloat16* __restrict__ Cl,
    int M, int N, int K, float scale)
{
    __shared__ __nv_bfloat16 sAh[128][40];
    __shared__ __nv_bfloat16 sAl[128][40];
    __shared__ __nv_bfloat16 sBh[128][40];
    __shared__ __nv_bfloat16 sBl[128][40];

    const int tid  = threadIdx.x;
    const int lane = tid & 31;
    const int w    = tid >> 5;
    const int g    = lane >> 2;
    const int t    = lane & 3;
    const int wm   = w & 3;     // m-slab (32 rows)
    const int wn   = w >> 2;    // n-slab (64 cols)

    const int mBlk = blockIdx.y << 7;
    const int nBlk = blockIdx.x << 7;

    float acc[2][8][4];
#pragma unroll
    for (int mt = 0; mt < 2; mt++)
#pragma unroll
        for (int nt = 0; nt < 8; nt++)
#pragma unroll
            for (int e = 0; e < 4; e++) acc[mt][nt][e] = 0.f;

    for (int k0 = 0; k0 < K; k0 += 32) {
        __syncthreads();
#pragma unroll
        for (int i = 0; i < 2; i++) {
            int idx = tid + 256 * i;             // 0..511
            int r = idx >> 2, c = (idx & 3) << 3;
            long ao = (long)(mBlk + r) * K + k0 + c;
            long bo = (long)(nBlk + r) * K + k0 + c;
            *(uint4*)&sAh[r][c] = *(const uint4*)(Ah + ao);
            *(uint4*)&sAl[r][c] = *(const uint4*)(Al + ao);
            *(uint4*)&sBh[r][c] = *(const uint4*)(Bh + bo);
            *(uint4*)&sBl[r][c] = *(const uint4*)(Bl + bo);
        }
        __syncthreads();

#pragma unroll
        for (int ks = 0; ks < 2; ks++) {
            const int kc = 16 * ks + 2 * t;
            unsigned afh[2][4], afl[2][4];
#pragma unroll
            for (int mt = 0; mt < 2; mt++) {
                int row = wm * 32 + mt * 16;
                afh[mt][0] = *(const unsigned*)&sAh[row + g][kc];
                afh[mt][1] = *(const unsigned*)&sAh[row + g + 8][kc];
                afh[mt][2] = *(const unsigned*)&sAh[row + g][kc + 8];
                afh[mt][3] = *(const unsigned*)&sAh[row + g + 8][kc + 8];
                afl[mt][0] = *(const unsigned*)&sAl[row + g][kc];
                afl[mt][1] = *(const unsigned*)&sAl[row + g + 8][kc];
                afl[mt][2] = *(const unsigned*)&sAl[row + g][kc + 8];
                afl[mt][3] = *(const unsigned*)&sAl[row + g + 8][kc + 8];
            }
#pragma unroll
            for (int nt = 0; nt < 8; nt++) {
                int col = wn * 64 + nt * 8 + g;
                unsigned bh0 = *(const unsigned*)&sBh[col][kc];
                unsigned bh1 = *(const unsigned*)&sBh[col][kc + 8];
                unsigned bl0 = *(const unsigned*)&sBl[col][kc];
                unsigned bl1 = *(const unsigned*)&sBl[col][kc + 8];
#pragma unroll
                for (int mt = 0; mt < 2; mt++) {
                    mma_bf16(acc[mt][nt], afh[mt], bh0, bh1);
                    mma_bf16(acc[mt][nt], afh[mt], bl0, bl1);
                    mma_bf16(acc[mt][nt], afl[mt], bh0, bh1);
                }
            }
        }
    }

    // ---- epilogue ----
#pragma unroll
    for (int mt = 0; mt < 2; mt++) {
#pragma unroll
        for (int nt = 0; nt < 8; nt++) {
            int r0 = mBlk + wm * 32 + mt * 16 + g;
            int cb = nBlk + wn * 64 + nt * 8 + 2 * t;
#pragma unroll
            for (int half = 0; half < 2; half++) {
                int row = r0 + 8 * half;
                float v0 = acc[mt][nt][2 * half];
                float v1 = acc[mt][nt][2 * half + 1];
                if (MODE == 0) {
                    float2 o;
                    o.x = v0 + bias[cb];
                    o.y = v1 + bias[cb + 1];
                    *(float2*)(Cf + (long)row * N + cb) = o;
                } else if (MODE == 1) {
                    __nv_bfloat162 H, L;
                    split1(v0 * scale, H.x, L.x);
                    split1(v1 * scale, H.y, L.y);
                    long o = (long)row * N + cb;
                    *(__nv_bfloat162*)(Ch + o) = H;
                    *(__nv_bfloat162*)(Cl + o) = L;
                } else {   // MODE 2: V transposed per head -> [b][h][d][k]
                    int b = row >> 12, k = row & 4095;
#pragma unroll
                    for (int e = 0; e < 2; e++) {
                        int col = cb + e;
                        int hh = col >> 6, d = col & 63;
                        long o = (((long)(b * NH + hh) * NDH + d) * NKL) + k;
                        float v = e ? v1 : v0;
                        __nv_bfloat16 vh, vl;
                        split1(v, vh, vl);
                        Ch[o] = vh; Cl[o] = vl;
                    }
                }
            }
        }
    }
}

// ---------------------------------------------------------------------------
// bf16-split flash attention on mma.sync.m16n8k16 (from R11; epilogue now
// writes O as bf16 hi/lo split for the tensor-core output projection).
// ---------------------------------------------------------------------------
__global__ __launch_bounds__(128) void attn_mma_kernel(
    const __nv_bfloat16* __restrict__ Qh, const __nv_bfloat16* __restrict__ Ql,
    const __nv_bfloat16* __restrict__ Kh, const __nv_bfloat16* __restrict__ Kl,
    const __nv_bfloat16* __restrict__ Vh, const __nv_bfloat16* __restrict__ Vl,
    __nv_bfloat16* __restrict__ Oh, __nv_bfloat16* __restrict__ Ol)
{
    __shared__ __nv_bfloat16 sKh[64][72];
    __shared__ __nv_bfloat16 sKl[64][72];
    __shared__ __nv_bfloat16 sVh[64][72];   // V transposed: [d][k]
    __shared__ __nv_bfloat16 sVl[64][72];

    const int tid  = threadIdx.x;
    const int lane = tid & 31;
    const int w    = tid >> 5;
    const int g    = lane >> 2;
    const int t    = lane & 3;

    const int qt = blockIdx.x, h = blockIdx.y, b = blockIdx.z;

    // ---- Q fragments in registers (constant across key loop) ----
    unsigned qfh[4][4], qfl[4][4];
    {
        const long qoff = ((long)(b * NQL + qt * 64 + w * 16)) * NIN + h * NDH;
        const __nv_bfloat16* qh = Qh + qoff;
        const __nv_bfloat16* ql = Ql + qoff;
#pragma unroll
        for (int j = 0; j < 4; j++) {
            int d0 = 16 * j + 2 * t;
            qfh[j][0] = *(const unsigned*)(qh + (long)g * NIN + d0);
            qfh[j][1] = *(const unsigned*)(qh + (long)(g + 8) * NIN + d0);
            qfh[j][2] = *(const unsigned*)(qh + (long)g * NIN + d0 + 8);
            qfh[j][3] = *(const unsigned*)(qh + (long)(g + 8) * NIN + d0 + 8);
            qfl[j][0] = *(const unsigned*)(ql + (long)g * NIN + d0);
            qfl[j][1] = *(const unsigned*)(ql + (long)(g + 8) * NIN + d0);
            qfl[j][2] = *(const unsigned*)(ql + (long)g * NIN + d0 + 8);
            qfl[j][3] = *(const unsigned*)(ql + (long)(g + 8) * NIN + d0 + 8);
        }
    }

    float o[8][4];
#pragma unroll
    for (int ct = 0; ct < 8; ct++)
#pragma unroll
        for (int e = 0; e < 4; e++) o[ct][e] = 0.f;
    float m0 = -1e30f, m1 = -1e30f, l0 = 0.f, l1 = 0.f;

    const __nv_bfloat16* kbh = Kh + (long)b * NKL * NIN + h * NDH;
    const __nv_bfloat16* kbl = Kl + (long)b * NKL * NIN + h * NDH;
    const __nv_bfloat16* vbh = Vh + (long)(b * NH + h) * NDH * NKL;
    const __nv_bfloat16* vbl = Vl + (long)(b * NH + h) * NDH * NKL;

    for (int kt = 0; kt < NKL / 64; kt++) {
        __syncthreads();
#pragma unroll
        for (int i = 0; i < 4; i++) {
            int c  = tid + 128 * i;
            int r  = c >> 3, c8 = c & 7;
            long koff = (long)(kt * 64 + r) * NIN + c8 * 8;
            long voff = (long)r * NKL + kt * 64 + c8 * 8;
            *(uint4*)&sKh[r][c8 * 8] = *(const uint4*)(kbh + koff);
            *(uint4*)&sKl[r][c8 * 8] = *(const uint4*)(kbl + koff);
            *(uint4*)&sVh[r][c8 * 8] = *(const uint4*)(vbh + voff);
            *(uint4*)&sVl[r][c8 * 8] = *(const uint4*)(vbl + voff);
        }
        __syncthreads();

        // ---- S = Q @ K^T (bf16x3) ----
        float s[8][4];
#pragma unroll
        for (int nt = 0; nt < 8; nt++) {
            s[nt][0] = s[nt][1] = s[nt][2] = s[nt][3] = 0.f;
#pragma unroll
            for (int j = 0; j < 4; j++) {
                int row = 8 * nt + g, col = 16 * j + 2 * t;
                unsigned bh0 = *(const unsigned*)&sKh[row][col];
                unsigned bh1 = *(const unsigned*)&sKh[row][col + 8];
                unsigned bl0 = *(const unsigned*)&sKl[row][col];
                unsigned bl1 = *(const unsigned*)&sKl[row][col + 8];
                mma_bf16(s[nt], qfh[j], bh0, bh1);
                mma_bf16(s[nt], qfh[j], bl0, bl1);
                mma_bf16(s[nt], qfl[j], bh0, bh1);
            }
        }

        // ---- online softmax ----
        float mt0 = -1e30f, mt1 = -1e30f;
#pragma unroll
        for (int nt = 0; nt < 8; nt++) {
            mt0 = fmaxf(mt0, fmaxf(s[nt][0], s[nt][1]));
            mt1 = fmaxf(mt1, fmaxf(s[nt][2], s[nt][3]));
        }
        mt0 = fmaxf(mt0, __shfl_xor_sync(0xffffffffu, mt0, 1));
        mt0 = fmaxf(mt0, __shfl_xor_sync(0xffffffffu, mt0, 2));
        mt1 = fmaxf(mt1, __shfl_xor_sync(0xffffffffu, mt1, 1));
        mt1 = fmaxf(mt1, __shfl_xor_sync(0xffffffffu, mt1, 2));
        float mn0 = fmaxf(m0, mt0), mn1 = fmaxf(m1, mt1);
        float cr0 = __expf(m0 - mn0), cr1 = __expf(m1 - mn1);
        m0 = mn0; m1 = mn1;

        float rs0 = 0.f, rs1 = 0.f;
        unsigned ph[8][2], pl[8][2];
#pragma unroll
        for (int nt = 0; nt < 8; nt++) {
            float p0 = __expf(s[nt][0] - m0), p1 = __expf(s[nt][1] - m0);
            float p2 = __expf(s[nt][2] - m1), p3 = __expf(s[nt][3] - m1);
            rs0 += p0 + p1; rs1 += p2 + p3;
            __nv_bfloat162 H, L;
            split1(p0, H.x, L.x); split1(p1, H.y, L.y);
            ph[nt][0] = *(unsigned*)&H; pl[nt][0] = *(unsigned*)&L;
            split1(p2, H.x, L.x); split1(p3, H.y, L.y);
            ph[nt][1] = *(unsigned*)&H; pl[nt][1] = *(unsigned*)&L;
        }
        rs0 += __shfl_xor_sync(0xffffffffu, rs0, 1);
        rs0 += __shfl_xor_sync(0xffffffffu, rs0, 2);
        rs1 += __shfl_xor_sync(0xffffffffu, rs1, 1);
        rs1 += __shfl_xor_sync(0xffffffffu, rs1, 2);
        l0 = l0 * cr0 + rs0;
        l1 = l1 * cr1 + rs1;
#pragma unroll
        for (int ct = 0; ct < 8; ct++) {
            o[ct][0] *= cr0; o[ct][1] *= cr0;
            o[ct][2] *= cr1; o[ct][3] *= cr1;
        }

        // ---- O += P @ V (bf16x3) ----
#pragma unroll
        for (int j = 0; j < 4; j++) {
            unsigned ah[4] = {ph[2 * j][0], ph[2 * j][1],
                              ph[2 * j + 1][0], ph[2 * j + 1][1]};
            unsigned al[4] = {pl[2 * j][0], pl[2 * j][1],
                              pl[2 * j + 1][0], pl[2 * j + 1][1]};
#pragma unroll
            for (int ct = 0; ct < 8; ct++) {
                int row = 8 * ct + g, col = 16 * j + 2 * t;
                unsigned vh0 = *(const unsigned*)&sVh[row][col];
                unsigned vh1 = *(const unsigned*)&sVh[row][col + 8];
                unsigned vl0 = *(const unsigned*)&sVl[row][col];
                unsigned vl1 = *(const unsigned*)&sVl[row][col + 8];
                mma_bf16(o[ct], ah, vh0, vh1);
                mma_bf16(o[ct], ah, vl0, vl1);
                mma_bf16(o[ct], al, vh0, vh1);
            }
        }
    }

    // ---- epilogue: normalize, split to bf16 hi/lo, write Oh/Ol ----
    float i0 = 1.f / l0, i1 = 1.f / l1;
    const long obase = ((long)(b * NQL + qt * 64 + w * 16)) * NIN + h * NDH;
#pragma unroll
    for (int ct = 0; ct < 8; ct++) {
        int cc = 8 * ct + 2 * t;
        __nv_bfloat162 H, L;
        split1(o[ct][0] * i0, H.x, L.x);
        split1(o[ct][1] * i0, H.y, L.y);
        long o0 = obase + (long)g * NIN + cc;
        *(__nv_bfloat162*)(Oh + o0) = H;
        *(__nv_bfloat162*)(Ol + o0) = L;
        split1(o[ct][2] * i1, H.x, L.x);
        split1(o[ct][3] * i1, H.y, L.y);
        long o1 = obase + (long)(g + 8) * NIN + cc;
        *(__nv_bfloat162*)(Oh + o1) = H;
        *(__nv_bfloat162*)(Ol + o1) = L;
    }
}

// ---------------------------------------------------------------------------
// Launch pipeline (graph-capturable: kernel launches only)
// ---------------------------------------------------------------------------
extern "C" void kernel_launch(void* const* d_in, const int* in_sizes, int n_in,
                              void* d_out, int out_size)
{
    (void)in_sizes; (void)n_in; (void)out_size;
    const float* x   = (const float*)d_in[0];
    const float* ctx = (const float*)d_in[1];
    const float* Wq  = (const float*)d_in[2];
    const float* Wk  = (const float*)d_in[3];
    const float* Wv  = (const float*)d_in[4];
    const float* Wo  = (const float*)d_in[5];
    const float* bo  = (const float*)d_in[6];
    float* out = (float*)d_out;

    __nv_bfloat16 *Xh, *Xl, *Ch, *Cl, *Qh, *Ql, *Kh, *Kl, *Vh, *Vl, *Oh, *Ol;
    __nv_bfloat16 *Wqh, *Wql, *Wkh, *Wkl, *Wvh, *Wvl, *Woh, *Wol;
    cudaGetSymbolAddress((void**)&Xh, g_Xh);  cudaGetSymbolAddress((void**)&Xl, g_Xl);
    cudaGetSymbolAddress((void**)&Ch, g_Ch);  cudaGetSymbolAddress((void**)&Cl, g_Cl);
    cudaGetSymbolAddress((void**)&Qh, g_Qh);  cudaGetSymbolAddress((void**)&Ql, g_Ql);
    cudaGetSymbolAddress((void**)&Kh, g_Kh);  cudaGetSymbolAddress((void**)&Kl, g_Kl);
    cudaGetSymbolAddress((void**)&Vh, g_Vh);  cudaGetSymbolAddress((void**)&Vl, g_Vl);
    cudaGetSymbolAddress((void**)&Oh, g_Oh);  cudaGetSymbolAddress((void**)&Ol, g_Ol);
    cudaGetSymbolAddress((void**)&Wqh, g_Wqh); cudaGetSymbolAddress((void**)&Wql, g_Wql);
    cudaGetSymbolAddress((void**)&Wkh, g_Wkh); cudaGetSymbolAddress((void**)&Wkl, g_Wkl);
    cudaGetSymbolAddress((void**)&Wvh, g_Wvh); cudaGetSymbolAddress((void**)&Wvl, g_Wvl);
    cudaGetSymbolAddress((void**)&Woh, g_Woh); cudaGetSymbolAddress((void**)&Wol, g_Wol);

    const int MTOK = NB * NQL;   // 8192 token rows

    // Input & weight hi/lo splits
    const int nx4 = (MTOK * NQD) / 4;
    const int nc4 = (MTOK * NCD) / 4;
    split_kernel<<<(nx4 + 255) / 256, 256>>>(x,   Xh, Xl, nx4);
    split_kernel<<<(nc4 + 255) / 256, 256>>>(ctx, Ch, Cl, nc4);
    dim3 wb(32, 8);
    wsplit_kernel<<<dim3(NQD / 32, NIN / 32), wb>>>(Wq, Wqh, Wql, NQD, NIN);
    wsplit_kernel<<<dim3(NCD / 32, NIN / 32), wb>>>(Wk, Wkh, Wkl, NCD, NIN);
    wsplit_kernel<<<dim3(NCD / 32, NIN / 32), wb>>>(Wv, Wvh, Wvl, NCD, NIN);
    wsplit_kernel<<<dim3(NIN / 32, NQD / 32), wb>>>(Wo, Woh, Wol, NIN, NQD);

    // Projections on tensor cores (bf16x3), epilogue-fused output formats
    dim3 gp(NIN / 128, MTOK / 128);
    gemm3_kernel<1><<<gp, 256>>>(Xh, Xl, Wqh, Wql, nullptr, nullptr, Qh, Ql,
                                 MTOK, NIN, NQD, ATTN_SCALE);
    gemm3_kernel<1><<<gp, 256>>>(Ch, Cl, Wkh, Wkl, nullptr, nullptr, Kh, Kl,
                                 MTOK, NIN, NCD, 1.0f);
    gemm3_kernel<2><<<gp, 256>>>(Ch, Cl, Wvh, Wvl, nullptr, nullptr, Vh, Vl,
                                 MTOK, NIN, NCD, 1.0f);

    // Flash attention on tensor cores (emits bf16-split O)
    dim3 ga(NQL / 64, NH, NB);
    attn_mma_kernel<<<ga, 128>>>(Qh, Ql, Kh, Kl, Vh, Vl, Oh, Ol);

    // Output projection with bias (fp32 result)
    dim3 go(NQD / 128, MTOK / 128);
    gemm3_kernel<0><<<go, 256>>>(Oh, Ol, Woh, Wol, bo, out, nullptr, nullptr,
                                 MTOK, NQD, NIN, 1.0f);
}

// round 14
// speedup vs baseline: 2.9974x; 1.0004x over previous
#include <cuda_runtime.h>
#include <cuda_bf16.h>

// Problem constants (fixed shapes)
#define NB   2
#define NQL  4096
#define NKL  4096
#define NQD  512
#define NCD  768
#define NH   8
#define NDH  64
#define NIN  512            // H * DH
#define ATTN_SCALE 0.125f   // DH^-0.5

// Scratch (static device globals -- allocation-free per harness rules)
__device__ __nv_bfloat16 g_Xh[NB * NQL * NQD];
__device__ __nv_bfloat16 g_Xl[NB * NQL * NQD];
__device__ __nv_bfloat16 g_Ch[NB * NKL * NCD];
__device__ __nv_bfloat16 g_Cl[NB * NKL * NCD];
__device__ __nv_bfloat16 g_Qh[NB * NQL * NIN];
__device__ __nv_bfloat16 g_Ql[NB * NQL * NIN];
__device__ __nv_bfloat16 g_Kh[NB * NKL * NIN];
__device__ __nv_bfloat16 g_Kl[NB * NKL * NIN];
__device__ __nv_bfloat16 g_Vh[NB * NKL * NIN];   // transposed: [b][h][d][k]
__device__ __nv_bfloat16 g_Vl[NB * NKL * NIN];
__device__ __nv_bfloat16 g_Oh[NB * NQL * NIN];
__device__ __nv_bfloat16 g_Ol[NB * NQL * NIN];
__device__ __nv_bfloat16 g_Wqh[NQD * NIN];       // all weights transposed: [N][K]
__device__ __nv_bfloat16 g_Wql[NQD * NIN];
__device__ __nv_bfloat16 g_Wkh[NCD * NIN];
__device__ __nv_bfloat16 g_Wkl[NCD * NIN];
__device__ __nv_bfloat16 g_Wvh[NCD * NIN];
__device__ __nv_bfloat16 g_Wvl[NCD * NIN];
__device__ __nv_bfloat16 g_Woh[NIN * NQD];
__device__ __nv_bfloat16 g_Wol[NIN * NQD];

// ---------------------------------------------------------------------------
// bf16 m16n8k16 MMA (fp32 accumulate)
// ---------------------------------------------------------------------------
__device__ __forceinline__ void mma_bf16(float d[4], const unsigned a[4],
                                         unsigned b0, unsigned b1)
{
    asm volatile(
        "mma.sync.aligned.m16n8k16.row.col.f32.bf16.bf16.f32 "
        "{%0,%1,%2,%3}, {%4,%5,%6,%7}, {%8,%9}, {%0,%1,%2,%3};"
        : "+f"(d[0]), "+f"(d[1]), "+f"(d[2]), "+f"(d[3])
        : "r"(a[0]), "r"(a[1]), "r"(a[2]), "r"(a[3]), "r"(b0), "r"(b1));
}

__device__ __forceinline__ void split1(float v, __nv_bfloat16& h, __nv_bfloat16& l)
{
    h = __float2bfloat16(v);
    l = __float2bfloat16(v - __bfloat162float(h));
}

// ---------------------------------------------------------------------------
// fp32 -> bf16 hi/lo split (elementwise), float4-vectorized
// ---------------------------------------------------------------------------
__global__ __launch_bounds__(256) void split_kernel(
    const float* __restrict__ in, __nv_bfloat16* __restrict__ hi,
    __nv_bfloat16* __restrict__ lo, int n4)
{
    int i = blockIdx.x * 256 + threadIdx.x;
    if (i >= n4) return;
    float4 v = ((const float4*)in)[i];
    float f[4] = {v.x, v.y, v.z, v.w};
    __nv_bfloat162 H0, H1, L0, L1;
    split1(f[0], H0.x, L0.x); split1(f[1], H0.y, L0.y);
    split1(f[2], H1.x, L1.x); split1(f[3], H1.y, L1.y);
    uint2 uh, ul;
    uh.x = *(unsigned*)&H0; uh.y = *(unsigned*)&H1;
    ul.x = *(unsigned*)&L0; ul.y = *(unsigned*)&L1;
    ((uint2*)hi)[i] = uh;
    ((uint2*)lo)[i] = ul;
}

// ---------------------------------------------------------------------------
// Weight transpose + split: W[K][N] fp32 -> Wt[N][K] bf16 hi/lo
// ---------------------------------------------------------------------------
__global__ __launch_bounds__(256) void wsplit_kernel(
    const float* __restrict__ W, __nv_bfloat16* __restrict__ wh,
    __nv_bfloat16* __restrict__ wl, int K, int N)
{
    __shared__ float tile[32][33];
    const int k0 = blockIdx.x * 32, n0 = blockIdx.y * 32;
    for (int yy = threadIdx.y; yy < 32; yy += 8)
        tile[yy][threadIdx.x] = W[(long)(k0 + yy) * N + n0 + threadIdx.x];
    __syncthreads();
    for (int yy = threadIdx.y; yy < 32; yy += 8) {
        float x = tile[threadIdx.x][yy];      // = W[k0+tx][n0+yy]
        long o = (long)(n0 + yy) * K + k0 + threadIdx.x;
        __nv_bfloat16 hh, ll;
        split1(x, hh, ll);
        wh[o] = hh; wl[o] = ll;
    }
}

// ---------------------------------------------------------------------------
// bf16x3 GEMM on mma.sync: C[M,N] = (Ah+Al)[M,K] @ (Bh+Bl)[N,K]^T
// Block: 128x128 tile, BK=32, 256 threads = 8 warps (4 m-slabs x 2 n-slabs),
// each warp 32m x 64n = 2 m16 x 8 n8 fragments. Rows padded to 40 bf16
// (word pitch 20 -> fragment LDS banks 20g+t+4s cover all 32 banks).
// MODE 0: Cf = acc + bias (fp32).
// MODE 1: Ch/Cl = bf16 hi/lo split of acc*scale (same [M][N] layout).
// MODE 2: V-transposed split: acc at (token row, inner col) -> [b][h][d][k].
// ---------------------------------------------------------------------------
template <int MODE>
__global__ __launch_bounds__(256) void gemm3_kernel(
    const __nv_bfloat16* __restrict__ Ah, const __nv_bfloat16* __restrict__ Al,
    const __nv_bfloat16* __restrict__ Bh, const __nv_bfloat16* __restrict__ Bl,
    const float* __restrict__ bias, float* __restrict__ Cf,
    __nv_bfloat16* __restrict__ Ch, __nv_bfloat16* __restrict__ Cl,
    int M, int N, int K, float scale)
{
    __shared__ __nv_bfloat16 sAh[128][40];
    __shared__ __nv_bfloat16 sAl[128][40];
    __shared__ __nv_bfloat16 sBh[128][40];
    __shared__ __nv_bfloat16 sBl[128][40];

    const int tid  = threadIdx.x;
    const int lane = tid & 31;
    const int w    = tid >> 5;
    const int g    = lane >> 2;
    const int t    = lane & 3;
    const int wm   = w & 3;     // m-slab (32 rows)
    const int wn   = w >> 2;    // n-slab (64 cols)

    const int mBlk = blockIdx.y << 7;
    const int nBlk = blockIdx.x << 7;

    float acc[2][8][4];
#pragma unroll
    for (int mt = 0; mt < 2; mt++)
#pragma unroll
        for (int nt = 0; nt < 8; nt++)
#pragma unroll
            for (int e = 0; e < 4; e++) acc[mt][nt][e] = 0.f;

    for (int k0 = 0; k0 < K; k0 += 32) {
        __syncthreads();
#pragma unroll
        for (int i = 0; i < 2; i++) {
            int idx = tid + 256 * i;             // 0..511
            int r = idx >> 2, c = (idx & 3) << 3;
            long ao = (long)(mBlk + r) * K + k0 + c;
            long bo = (long)(nBlk + r) * K + k0 + c;
            *(uint4*)&sAh[r][c] = *(const uint4*)(Ah + ao);
            *(uint4*)&sAl[r][c] = *(const uint4*)(Al + ao);
            *(uint4*)&sBh[r][c] = *(const uint4*)(Bh + bo);
            *(uint4*)&sBl[r][c] = *(const uint4*)(Bl + bo);
        }
        __syncthreads();

#pragma unroll
        for (int ks = 0; ks < 2; ks++) {
            const int kc = 16 * ks + 2 * t;
            unsigned afh[2][4], afl[2][4];
#pragma unroll
            for (int mt = 0; mt < 2; mt++) {
                int row = wm * 32 + mt * 16;
                afh[mt][0] = *(const unsigned*)&sAh[row + g][kc];
                afh[mt][1] = *(const unsigned*)&sAh[row + g + 8][kc];
                afh[mt][2] = *(const unsigned*)&sAh[row + g][kc + 8];
                afh[mt][3] = *(const unsigned*)&sAh[row + g + 8][kc + 8];
                afl[mt][0] = *(const unsigned*)&sAl[row + g][kc];
                afl[mt][1] = *(const unsigned*)&sAl[row + g + 8][kc];
                afl[mt][2] = *(const unsigned*)&sAl[row + g][kc + 8];
                afl[mt][3] = *(const unsigned*)&sAl[row + g + 8][kc + 8];
            }
#pragma unroll
            for (int nt = 0; nt < 8; nt++) {
                int col = wn * 64 + nt * 8 + g;
                unsigned bh0 = *(const unsigned*)&sBh[col][kc];
                unsigned bh1 = *(const unsigned*)&sBh[col][kc + 8];
                unsigned bl0 = *(const unsigned*)&sBl[col][kc];
                unsigned bl1 = *(const unsigned*)&sBl[col][kc + 8];
#pragma unroll
                for (int mt = 0; mt < 2; mt++) {
                    mma_bf16(acc[mt][nt], afh[mt], bh0, bh1);
                    mma_bf16(acc[mt][nt], afh[mt], bl0, bl1);
                    mma_bf16(acc[mt][nt], afl[mt], bh0, bh1);
                }
            }
        }
    }

    // ---- epilogue ----
#pragma unroll
    for (int mt = 0; mt < 2; mt++) {
#pragma unroll
        for (int nt = 0; nt < 8; nt++) {
            int r0 = mBlk + wm * 32 + mt * 16 + g;
            int cb = nBlk + wn * 64 + nt * 8 + 2 * t;
#pragma unroll
            for (int half = 0; half < 2; half++) {
                int row = r0 + 8 * half;
                float v0 = acc[mt][nt][2 * half];
                float v1 = acc[mt][nt][2 * half + 1];
                if (MODE == 0) {
                    float2 o;
                    o.x = v0 + bias[cb];
                    o.y = v1 + bias[cb + 1];
                    *(float2*)(Cf + (long)row * N + cb) = o;
                } else if (MODE == 1) {
                    __nv_bfloat162 H, L;
                    split1(v0 * scale, H.x, L.x);
                    split1(v1 * scale, H.y, L.y);
                    long o = (long)row * N + cb;
                    *(__nv_bfloat162*)(Ch + o) = H;
                    *(__nv_bfloat162*)(Cl + o) = L;
                } else {   // MODE 2: V transposed per head -> [b][h][d][k]
                    int b = row >> 12, k = row & 4095;
#pragma unroll
                    for (int e = 0; e < 2; e++) {
                        int col = cb + e;
                        int hh = col >> 6, d = col & 63;
                        long o = (((long)(b * NH + hh) * NDH + d) * NKL) + k;
                        float v = e ? v1 : v0;
                        __nv_bfloat16 vh, vl;
                        split1(v, vh, vl);
                        Ch[o] = vh; Cl[o] = vl;
                    }
                }
            }
        }
    }
}

// ---------------------------------------------------------------------------
// bf16-split flash attention on mma.sync.m16n8k16 (from R11; epilogue now
// writes O as bf16 hi/lo split for the tensor-core output projection).
// ---------------------------------------------------------------------------
__global__ __launch_bounds__(128) void attn_mma_kernel(
    const __nv_bfloat16* __restrict__ Qh, const __nv_bfloat16* __restrict__ Ql,
    const __nv_bfloat16* __restrict__ Kh, const __nv_bfloat16* __restrict__ Kl,
    const __nv_bfloat16* __restrict__ Vh, const __nv_bfloat16* __restrict__ Vl,
    __nv_bfloat16* __restrict__ Oh, __nv_bfloat16* __restrict__ Ol)
{
    __shared__ __nv_bfloat16 sKh[64][72];
    __shared__ __nv_bfloat16 sKl[64][72];
    __shared__ __nv_bfloat16 sVh[64][72];   // V transposed: [d][k]
    __shared__ __nv_bfloat16 sVl[64][72];

    const int tid  = threadIdx.x;
    const int lane = tid & 31;
    const int w    = tid >> 5;
    const int g    = lane >> 2;
    const int t    = lane & 3;

    const int qt = blockIdx.x, h = blockIdx.y, b = blockIdx.z;

    // ---- Q fragments in registers (constant across key loop) ----
    unsigned qfh[4][4], qfl[4][4];
    {
        const long qoff = ((long)(b * NQL + qt * 64 + w * 16)) * NIN + h * NDH;
        const __nv_bfloat16* qh = Qh + qoff;
        const __nv_bfloat16* ql = Ql + qoff;
#pragma unroll
        for (int j = 0; j < 4; j++) {
            int d0 = 16 * j + 2 * t;
            qfh[j][0] = *(const unsigned*)(qh + (long)g * NIN + d0);
            qfh[j][1] = *(const unsigned*)(qh + (long)(g + 8) * NIN + d0);
            qfh[j][2] = *(const unsigned*)(qh + (long)g * NIN + d0 + 8);
            qfh[j][3] = *(const unsigned*)(qh + (long)(g + 8) * NIN + d0 + 8);
            qfl[j][0] = *(const unsigned*)(ql + (long)g * NIN + d0);
            qfl[j][1] = *(const unsigned*)(ql + (long)(g + 8) * NIN + d0);
            qfl[j][2] = *(const unsigned*)(ql + (long)g * NIN + d0 + 8);
            qfl[j][3] = *(const unsigned*)(ql + (long)(g + 8) * NIN + d0 + 8);
        }
    }

    float o[8][4];
#pragma unroll
    for (int ct = 0; ct < 8; ct++)
#pragma unroll
        for (int e = 0; e < 4; e++) o[ct][e] = 0.f;
    float m0 = -1e30f, m1 = -1e30f, l0 = 0.f, l1 = 0.f;

    const __nv_bfloat16* kbh = Kh + (long)b * NKL * NIN + h * NDH;
    const __nv_bfloat16* kbl = Kl + (long)b * NKL * NIN + h * NDH;
    const __nv_bfloat16* vbh = Vh + (long)(b * NH + h) * NDH * NKL;
    const __nv_bfloat16* vbl = Vl + (long)(b * NH + h) * NDH * NKL;

    for (int kt = 0; kt < NKL / 64; kt++) {
        __syncthreads();
#pragma unroll
        for (int i = 0; i < 4; i++) {
            int c  = tid + 128 * i;
            int r  = c >> 3, c8 = c & 7;
            long koff = (long)(kt * 64 + r) * NIN + c8 * 8;
            long voff = (long)r * NKL + kt * 64 + c8 * 8;
            *(uint4*)&sKh[r][c8 * 8] = *(const uint4*)(kbh + koff);
            *(uint4*)&sKl[r][c8 * 8] = *(const uint4*)(kbl + koff);
            *(uint4*)&sVh[r][c8 * 8] = *(const uint4*)(vbh + voff);
            *(uint4*)&sVl[r][c8 * 8] = *(const uint4*)(vbl + voff);
        }
        __syncthreads();

        // ---- S = Q @ K^T (bf16x3) ----
        float s[8][4];
#pragma unroll
        for (int nt = 0; nt < 8; nt++) {
            s[nt][0] = s[nt][1] = s[nt][2] = s[nt][3] = 0.f;
#pragma unroll
            for (int j = 0; j < 4; j++) {
                int row = 8 * nt + g, col = 16 * j + 2 * t;
                unsigned bh0 = *(const unsigned*)&sKh[row][col];
                unsigned bh1 = *(const unsigned*)&sKh[row][col + 8];
                unsigned bl0 = *(const unsigned*)&sKl[row][col];
                unsigned bl1 = *(const unsigned*)&sKl[row][col + 8];
                mma_bf16(s[nt], qfh[j], bh0, bh1);
                mma_bf16(s[nt], qfh[j], bl0, bl1);
                mma_bf16(s[nt], qfl[j], bh0, bh1);
            }
        }

        // ---- online softmax ----
        float mt0 = -1e30f, mt1 = -1e30f;
#pragma unroll
        for (int nt = 0; nt < 8; nt++) {
            mt0 = fmaxf(mt0, fmaxf(s[nt][0], s[nt][1]));
            mt1 = fmaxf(mt1, fmaxf(s[nt][2], s[nt][3]));
        }
        mt0 = fmaxf(mt0, __shfl_xor_sync(0xffffffffu, mt0, 1));
        mt0 = fmaxf(mt0, __shfl_xor_sync(0xffffffffu, mt0, 2));
        mt1 = fmaxf(mt1, __shfl_xor_sync(0xffffffffu, mt1, 1));
        mt1 = fmaxf(mt1, __shfl_xor_sync(0xffffffffu, mt1, 2));
        float mn0 = fmaxf(m0, mt0), mn1 = fmaxf(m1, mt1);
        float cr0 = __expf(m0 - mn0), cr1 = __expf(m1 - mn1);
        m0 = mn0; m1 = mn1;

        float rs0 = 0.f, rs1 = 0.f;
        unsigned ph[8][2], pl[8][2];
#pragma unroll
        for (int nt = 0; nt < 8; nt++) {
            float p0 = __expf(s[nt][0] - m0), p1 = __expf(s[nt][1] - m0);
            float p2 = __expf(s[nt][2] - m1), p3 = __expf(s[nt][3] - m1);
            rs0 += p0 + p1; rs1 += p2 + p3;
            __nv_bfloat162 H, L;
            split1(p0, H.x, L.x); split1(p1, H.y, L.y);
            ph[nt][0] = *(unsigned*)&H; pl[nt][0] = *(unsigned*)&L;
            split1(p2, H.x, L.x); split1(p3, H.y, L.y);
            ph[nt][1] = *(unsigned*)&H; pl[nt][1] = *(unsigned*)&L;
        }
        rs0 += __shfl_xor_sync(0xffffffffu, rs0, 1);
        rs0 += __shfl_xor_sync(0xffffffffu, rs0, 2);
        rs1 += __shfl_xor_sync(0xffffffffu, rs1, 1);
        rs1 += __shfl_xor_sync(0xffffffffu, rs1, 2);
        l0 = l0 * cr0 + rs0;
        l1 = l1 * cr1 + rs1;
#pragma unroll
        for (int ct = 0; ct < 8; ct++) {
            o[ct][0] *= cr0; o[ct][1] *= cr0;
            o[ct][2] *= cr1; o[ct][3] *= cr1;
        }

        // ---- O += P @ V (bf16x3) ----
#pragma unroll
        for (int j = 0; j < 4; j++) {
            unsigned ah[4] = {ph[2 * j][0], ph[2 * j][1],
                              ph[2 * j + 1][0], ph[2 * j + 1][1]};
            unsigned al[4] = {pl[2 * j][0], pl[2 * j][1],
                              pl[2 * j + 1][0], pl[2 * j + 1][1]};
#pragma unroll
            for (int ct = 0; ct < 8; ct++) {
                int row = 8 * ct + g, col = 16 * j + 2 * t;
                unsigned vh0 = *(const unsigned*)&sVh[row][col];
                unsigned vh1 = *(const unsigned*)&sVh[row][col + 8];
                unsigned vl0 = *(const unsigned*)&sVl[row][col];
                unsigned vl1 = *(const unsigned*)&sVl[row][col + 8];
                mma_bf16(o[ct], ah, vh0, vh1);
                mma_bf16(o[ct], ah, vl0, vl1);
                mma_bf16(o[ct], al, vh0, vh1);
            }
        }
    }

    // ---- epilogue: normalize, split to bf16 hi/lo, write Oh/Ol ----
    float i0 = 1.f / l0, i1 = 1.f / l1;
    const long obase = ((long)(b * NQL + qt * 64 + w * 16)) * NIN + h * NDH;
#pragma unroll
    for (int ct = 0; ct < 8; ct++) {
        int cc = 8 * ct + 2 * t;
        __nv_bfloat162 H, L;
        split1(o[ct][0] * i0, H.x, L.x);
        split1(o[ct][1] * i0, H.y, L.y);
        long o0 = obase + (long)g * NIN + cc;
        *(__nv_bfloat162*)(Oh + o0) = H;
        *(__nv_bfloat162*)(Ol + o0) = L;
        split1(o[ct][2] * i1, H.x, L.x);
        split1(o[ct][3] * i1, H.y, L.y);
        long o1 = obase + (long)(g + 8) * NIN + cc;
        *(__nv_bfloat162*)(Oh + o1) = H;
        *(__nv_bfloat162*)(Ol + o1) = L;
    }
}

// ---------------------------------------------------------------------------
// Launch pipeline (graph-capturable: kernel launches only)
// ---------------------------------------------------------------------------
extern "C" void kernel_launch(void* const* d_in, const int* in_sizes, int n_in,
                              void* d_out, int out_size)
{
    (void)in_sizes; (void)n_in; (void)out_size;
    const float* x   = (const float*)d_in[0];
    const float* ctx = (const float*)d_in[1];
    const float* Wq  = (const float*)d_in[2];
    const float* Wk  = (const float*)d_in[3];
    const float* Wv  = (const float*)d_in[4];
    const float* Wo  = (const float*)d_in[5];
    const float* bo  = (const float*)d_in[6];
    float* out = (float*)d_out;

    __nv_bfloat16 *Xh, *Xl, *Ch, *Cl, *Qh, *Ql, *Kh, *Kl, *Vh, *Vl, *Oh, *Ol;
    __nv_bfloat16 *Wqh, *Wql, *Wkh, *Wkl, *Wvh, *Wvl, *Woh, *Wol;
    cudaGetSymbolAddress((void**)&Xh, g_Xh);  cudaGetSymbolAddress((void**)&Xl, g_Xl);
    cudaGetSymbolAddress((void**)&Ch, g_Ch);  cudaGetSymbolAddress((void**)&Cl, g_Cl);
    cudaGetSymbolAddress((void**)&Qh, g_Qh);  cudaGetSymbolAddress((void**)&Ql, g_Ql);
    cudaGetSymbolAddress((void**)&Kh, g_Kh);  cudaGetSymbolAddress((void**)&Kl, g_Kl);
    cudaGetSymbolAddress((void**)&Vh, g_Vh);  cudaGetSymbolAddress((void**)&Vl, g_Vl);
    cudaGetSymbolAddress((void**)&Oh, g_Oh);  cudaGetSymbolAddress((void**)&Ol, g_Ol);
    cudaGetSymbolAddress((void**)&Wqh, g_Wqh); cudaGetSymbolAddress((void**)&Wql, g_Wql);
    cudaGetSymbolAddress((void**)&Wkh, g_Wkh); cudaGetSymbolAddress((void**)&Wkl, g_Wkl);
    cudaGetSymbolAddress((void**)&Wvh, g_Wvh); cudaGetSymbolAddress((void**)&Wvl, g_Wvl);
    cudaGetSymbolAddress((void**)&Woh, g_Woh); cudaGetSymbolAddress((void**)&Wol, g_Wol);

    const int MTOK = NB * NQL;   // 8192 token rows

    // Input & weight hi/lo splits
    const int nx4 = (MTOK * NQD) / 4;
    const int nc4 = (MTOK * NCD) / 4;
    split_kernel<<<(nx4 + 255) / 256, 256>>>(x,   Xh, Xl, nx4);
    split_kernel<<<(nc4 + 255) / 256, 256>>>(ctx, Ch, Cl, nc4);
    dim3 wb(32, 8);
    wsplit_kernel<<<dim3(NQD / 32, NIN / 32), wb>>>(Wq, Wqh, Wql, NQD, NIN);
    wsplit_kernel<<<dim3(NCD / 32, NIN / 32), wb>>>(Wk, Wkh, Wkl, NCD, NIN);
    wsplit_kernel<<<dim3(NCD / 32, NIN / 32), wb>>>(Wv, Wvh, Wvl, NCD, NIN);
    wsplit_kernel<<<dim3(NIN / 32, NQD / 32), wb>>>(Wo, Woh, Wol, NIN, NQD);

    // Projections on tensor cores (bf16x3), epilogue-fused output formats
    dim3 gp(NIN / 128, MTOK / 128);
    gemm3_kernel<1><<<gp, 256>>>(Xh, Xl, Wqh, Wql, nullptr, nullptr, Qh, Ql,
                                 MTOK, NIN, NQD, ATTN_SCALE);
    gemm3_kernel<1><<<gp, 256>>>(Ch, Cl, Wkh, Wkl, nullptr, nullptr, Kh, Kl,
                                 MTOK, NIN, NCD, 1.0f);
    gemm3_kernel<2><<<gp, 256>>>(Ch, Cl, Wvh, Wvl, nullptr, nullptr, Vh, Vl,
                                 MTOK, NIN, NCD, 1.0f);

    // Flash attention on tensor cores (emits bf16-split O)
    dim3 ga(NQL / 64, NH, NB);
    attn_mma_kernel<<<ga, 128>>>(Qh, Ql, Kh, Kl, Vh, Vl, Oh, Ol);

    // Output projection with bias (fp32 result)
    dim3 go(NQD / 128, MTOK / 128);
    gemm3_kernel<0><<<go, 256>>>(Oh, Ol, Woh, Wol, bo, out, nullptr, nullptr,
                                 MTOK, NQD, NIN, 1.0f);
}

// round 15
// speedup vs baseline: 4.0169x; 1.3401x over previous
#include <cuda_runtime.h>
#include <cuda_bf16.h>

// Problem constants (fixed shapes)
#define NB   2
#define NQL  4096
#define NKL  4096
#define NQD  512
#define NCD  768
#define NH   8
#define NDH  64
#define NIN  512            // H * DH
#define ATTN_SCALE 0.125f   // DH^-0.5

// Scratch (static device globals -- allocation-free per harness rules)
__device__ __nv_bfloat16 g_Xh[NB * NQL * NQD];
__device__ __nv_bfloat16 g_Xl[NB * NQL * NQD];
__device__ __nv_bfloat16 g_Ch[NB * NKL * NCD];
__device__ __nv_bfloat16 g_Cl[NB * NKL * NCD];
__device__ __nv_bfloat16 g_Qh[NB * NQL * NIN];
__device__ __nv_bfloat16 g_Ql[NB * NQL * NIN];
__device__ __nv_bfloat16 g_Kh[NB * NKL * NIN];
__device__ __nv_bfloat16 g_Kl[NB * NKL * NIN];
__device__ __nv_bfloat16 g_Vh[NB * NKL * NIN];   // transposed: [b][h][d][k]
__device__ __nv_bfloat16 g_Vl[NB * NKL * NIN];
__device__ __nv_bfloat16 g_Oh[NB * NQL * NIN];
__device__ __nv_bfloat16 g_Ol[NB * NQL * NIN];
__device__ __nv_bfloat16 g_Wqh[NQD * NIN];       // all weights transposed: [N][K]
__device__ __nv_bfloat16 g_Wql[NQD * NIN];
__device__ __nv_bfloat16 g_Wkh[NCD * NIN];
__device__ __nv_bfloat16 g_Wkl[NCD * NIN];
__device__ __nv_bfloat16 g_Wvh[NCD * NIN];
__device__ __nv_bfloat16 g_Wvl[NCD * NIN];
__device__ __nv_bfloat16 g_Woh[NIN * NQD];
__device__ __nv_bfloat16 g_Wol[NIN * NQD];

// ---------------------------------------------------------------------------
// Primitive helpers
// ---------------------------------------------------------------------------
__device__ __forceinline__ void mma_bf16(float d[4], const unsigned a[4],
                                         unsigned b0, unsigned b1)
{
    asm volatile(
        "mma.sync.aligned.m16n8k16.row.col.f32.bf16.bf16.f32 "
        "{%0,%1,%2,%3}, {%4,%5,%6,%7}, {%8,%9}, {%0,%1,%2,%3};"
        : "+f"(d[0]), "+f"(d[1]), "+f"(d[2]), "+f"(d[3])
        : "r"(a[0]), "r"(a[1]), "r"(a[2]), "r"(a[3]), "r"(b0), "r"(b1));
}

__device__ __forceinline__ void split1(float v, __nv_bfloat16& h, __nv_bfloat16& l)
{
    h = __float2bfloat16(v);
    l = __float2bfloat16(v - __bfloat162float(h));
}

__device__ __forceinline__ unsigned s2u(const void* p)
{
    return (unsigned)__cvta_generic_to_shared(p);
}

__device__ __forceinline__ void ldm_x4(unsigned r[4], unsigned addr)
{
    asm volatile("ldmatrix.sync.aligned.m8n8.x4.shared.b16 {%0,%1,%2,%3}, [%4];"
                 : "=r"(r[0]), "=r"(r[1]), "=r"(r[2]), "=r"(r[3]) : "r"(addr));
}

__device__ __forceinline__ void cp16(void* dst, const void* src)
{
    unsigned d = s2u(dst);
    asm volatile("cp.async.cg.shared.global [%0], [%1], 16;" :: "r"(d), "l"(src));
}
#define CP_COMMIT() asm volatile("cp.async.commit_group;")
#define CP_WAIT(N)  asm volatile("cp.async.wait_group %0;" :: "n"(N))

// ---------------------------------------------------------------------------
// fp32 -> bf16 hi/lo split (elementwise), float4-vectorized
// ---------------------------------------------------------------------------
__global__ __launch_bounds__(256) void split_kernel(
    const float* __restrict__ in, __nv_bfloat16* __restrict__ hi,
    __nv_bfloat16* __restrict__ lo, int n4)
{
    int i = blockIdx.x * 256 + threadIdx.x;
    if (i >= n4) return;
    float4 v = ((const float4*)in)[i];
    float f[4] = {v.x, v.y, v.z, v.w};
    __nv_bfloat162 H0, H1, L0, L1;
    split1(f[0], H0.x, L0.x); split1(f[1], H0.y, L0.y);
    split1(f[2], H1.x, L1.x); split1(f[3], H1.y, L1.y);
    uint2 uh, ul;
    uh.x = *(unsigned*)&H0; uh.y = *(unsigned*)&H1;
    ul.x = *(unsigned*)&L0; ul.y = *(unsigned*)&L1;
    ((uint2*)hi)[i] = uh;
    ((uint2*)lo)[i] = ul;
}

// ---------------------------------------------------------------------------
// Weight transpose + split: W[K][N] fp32 -> Wt[N][K] bf16 hi/lo
// ---------------------------------------------------------------------------
__global__ __launch_bounds__(256) void wsplit_kernel(
    const float* __restrict__ W, __nv_bfloat16* __restrict__ wh,
    __nv_bfloat16* __restrict__ wl, int K, int N)
{
    __shared__ float tile[32][33];
    const int k0 = blockIdx.x * 32, n0 = blockIdx.y * 32;
    for (int yy = threadIdx.y; yy < 32; yy += 8)
        tile[yy][threadIdx.x] = W[(long)(k0 + yy) * N + n0 + threadIdx.x];
    __syncthreads();
    for (int yy = threadIdx.y; yy < 32; yy += 8) {
        float x = tile[threadIdx.x][yy];      // = W[k0+tx][n0+yy]
        long o = (long)(n0 + yy) * K + k0 + threadIdx.x;
        __nv_bfloat16 hh, ll;
        split1(x, hh, ll);
        wh[o] = hh; wl[o] = ll;
    }
}

// ---------------------------------------------------------------------------
// bf16x3 GEMM on mma.sync: C[M,N] = (Ah+Al)[M,K] @ (Bh+Bl)[N,K]^T
// 128x128 tile, BK=32, 256 threads = 8 warps (4m x 2n slabs), warp 32m x 64n.
// cp.async 2-stage double buffer; ldmatrix.x4 fragment loads.
// Rows padded to 40 bf16 (pitch 80B): the 8 row-addresses of each 8x8
// ldmatrix matrix land on distinct bank groups -> conflict-free LDSM.
// MODE 0: Cf = acc + bias (fp32). MODE 1: bf16 hi/lo split of acc*scale.
// MODE 2: V-transposed split -> [b][h][d][k].
// ---------------------------------------------------------------------------
#define G3_TS   (128 * 40)            // elems per array per stage
#define G3_SMEM (2 * 4 * G3_TS * 2)   // bytes: 81920

#define G3_LOAD(st, k0) do {                                                  \
    __nv_bfloat16* p = smp + (st) * 4 * G3_TS;                                \
    _Pragma("unroll")                                                         \
    for (int i_ = 0; i_ < 2; i_++) {                                          \
        int r_ = lr + 64 * i_;                                                \
        long ao_ = (long)(mBlk + r_) * K + (k0) + lc;                         \
        long bo_ = (long)(nBlk + r_) * K + (k0) + lc;                         \
        cp16(p + r_ * 40 + lc,              Ah + ao_);                        \
        cp16(p + G3_TS + r_ * 40 + lc,      Al + ao_);                        \
        cp16(p + 2 * G3_TS + r_ * 40 + lc,  Bh + bo_);                        \
        cp16(p + 3 * G3_TS + r_ * 40 + lc,  Bl + bo_);                        \
    }                                                                         \
    CP_COMMIT(); } while (0)

template <int MODE>
__global__ __launch_bounds__(256) void gemm3_kernel(
    const __nv_bfloat16* __restrict__ Ah, const __nv_bfloat16* __restrict__ Al,
    const __nv_bfloat16* __restrict__ Bh, const __nv_bfloat16* __restrict__ Bl,
    const float* __restrict__ bias, float* __restrict__ Cf,
    __nv_bfloat16* __restrict__ Ch, __nv_bfloat16* __restrict__ Cl,
    int M, int N, int K, float scale)
{
    extern __shared__ __align__(16) char dynsmem[];
    __nv_bfloat16* smp = (__nv_bfloat16*)dynsmem;

    const int tid  = threadIdx.x;
    const int lane = tid & 31;
    const int w    = tid >> 5;
    const int g    = lane >> 2;
    const int t    = lane & 3;
    const int wm   = w & 3;     // m-slab (32 rows)
    const int wn   = w >> 2;    // n-slab (64 cols)

    const int mBlk = blockIdx.y << 7;
    const int nBlk = blockIdx.x << 7;

    // ldmatrix per-lane intra-fragment byte offsets (pitch 40 bf16 = 80 B)
    const unsigned lrow = lane & 7, lsel = lane >> 3;
    const unsigned fragA = ((lrow + 8 * (lsel & 1)) * 40 + 8 * (lsel >> 1)) * 2;
    const unsigned fragB = ((lrow + 8 * (lsel >> 1)) * 40 + 8 * (lsel & 1)) * 2;
    const unsigned base_u = s2u(smp);

    // cp.async load indexing
    const int lr = tid >> 2;            // 0..63
    const int lc = (tid & 3) << 3;      // 0,8,16,24

    float acc[2][8][4];
#pragma unroll
    for (int mt = 0; mt < 2; mt++)
#pragma unroll
        for (int nt = 0; nt < 8; nt++)
#pragma unroll
            for (int e = 0; e < 4; e++) acc[mt][nt][e] = 0.f;

    const int NKI = K >> 5;
    G3_LOAD(0, 0);

    for (int i = 0; i < NKI; i++) {
        if (i + 1 < NKI) { G3_LOAD((i + 1) & 1, (i + 1) * 32); CP_WAIT(1); }
        else             { CP_WAIT(0); }
        __syncthreads();

        const unsigned sb = base_u + (unsigned)(i & 1) * (4 * G3_TS * 2);
#pragma unroll
        for (int ks = 0; ks < 2; ks++) {
            const unsigned aoff = sb + ((wm * 32) * 40 + 16 * ks) * 2;
            unsigned afh[2][4], afl[2][4];
            ldm_x4(afh[0], aoff + fragA);
            ldm_x4(afh[1], aoff + 16 * 40 * 2 + fragA);
            ldm_x4(afl[0], aoff + G3_TS * 2 + fragA);
            ldm_x4(afl[1], aoff + G3_TS * 2 + 16 * 40 * 2 + fragA);
#pragma unroll
            for (int ntp = 0; ntp < 4; ntp++) {
                const unsigned boff =
                    sb + 2 * G3_TS * 2 + ((wn * 64 + ntp * 16) * 40 + 16 * ks) * 2;
                unsigned bh[4], bl[4];
                ldm_x4(bh, boff + fragB);
                ldm_x4(bl, boff + G3_TS * 2 + fragB);
#pragma unroll
                for (int mt = 0; mt < 2; mt++) {
                    mma_bf16(acc[mt][2 * ntp],     afh[mt], bh[0], bh[1]);
                    mma_bf16(acc[mt][2 * ntp],     afh[mt], bl[0], bl[1]);
                    mma_bf16(acc[mt][2 * ntp],     afl[mt], bh[0], bh[1]);
                    mma_bf16(acc[mt][2 * ntp + 1], afh[mt], bh[2], bh[3]);
                    mma_bf16(acc[mt][2 * ntp + 1], afh[mt], bl[2], bl[3]);
                    mma_bf16(acc[mt][2 * ntp + 1], afl[mt], bh[2], bh[3]);
                }
            }
        }
        __syncthreads();
    }

    // ---- epilogue ----
#pragma unroll
    for (int mt = 0; mt < 2; mt++) {
#pragma unroll
        for (int nt = 0; nt < 8; nt++) {
            int r0 = mBlk + wm * 32 + mt * 16 + g;
            int cb = nBlk + wn * 64 + nt * 8 + 2 * t;
#pragma unroll
            for (int half = 0; half < 2; half++) {
                int row = r0 + 8 * half;
                float v0 = acc[mt][nt][2 * half];
                float v1 = acc[mt][nt][2 * half + 1];
                if (MODE == 0) {
                    float2 o;
                    o.x = v0 + bias[cb];
                    o.y = v1 + bias[cb + 1];
                    *(float2*)(Cf + (long)row * N + cb) = o;
                } else if (MODE == 1) {
                    __nv_bfloat162 H, L;
                    split1(v0 * scale, H.x, L.x);
                    split1(v1 * scale, H.y, L.y);
                    long o = (long)row * N + cb;
                    *(__nv_bfloat162*)(Ch + o) = H;
                    *(__nv_bfloat162*)(Cl + o) = L;
                } else {   // MODE 2: V transposed per head -> [b][h][d][k]
                    int b = row >> 12, k = row & 4095;
#pragma unroll
                    for (int e = 0; e < 2; e++) {
                        int col = cb + e;
                        int hh = col >> 6, d = col & 63;
                        long o = (((long)(b * NH + hh) * NDH + d) * NKL) + k;
                        float v = e ? v1 : v0;
                        __nv_bfloat16 vh, vl;
                        split1(v, vh, vl);
                        Ch[o] = vh; Cl[o] = vl;
                    }
                }
            }
        }
    }
}

// ---------------------------------------------------------------------------
// bf16-split flash attention on mma.sync.m16n8k16.
// cp.async 2-stage double buffer for K/V tiles; ldmatrix.x4 fragment loads.
// Rows padded to 72 bf16 (144B pitch) -> conflict-free LDSM.
// ---------------------------------------------------------------------------
#define AT_AS   (64 * 72)             // elems per array per stage
#define AT_SMEM (2 * 4 * AT_AS * 2)   // bytes: 73728

#define AT_LOAD(st, kt) do {                                                  \
    __nv_bfloat16* p = smp + (st) * 4 * AT_AS;                                \
    _Pragma("unroll")                                                         \
    for (int i_ = 0; i_ < 4; i_++) {                                          \
        int r_ = lr + 16 * i_;                                                \
        long ko_ = (long)((kt) * 64 + r_) * NIN + lc;                         \
        long vo_ = (long)r_ * NKL + (kt) * 64 + lc;                           \
        cp16(p + r_ * 72 + lc,              kbh + ko_);                       \
        cp16(p + AT_AS + r_ * 72 + lc,      kbl + ko_);                       \
        cp16(p + 2 * AT_AS + r_ * 72 + lc,  vbh + vo_);                       \
        cp16(p + 3 * AT_AS + r_ * 72 + lc,  vbl + vo_);                       \
    }                                                                         \
    CP_COMMIT(); } while (0)

__global__ __launch_bounds__(128) void attn_mma_kernel(
    const __nv_bfloat16* __restrict__ Qh, const __nv_bfloat16* __restrict__ Ql,
    const __nv_bfloat16* __restrict__ Kh, const __nv_bfloat16* __restrict__ Kl,
    const __nv_bfloat16* __restrict__ Vh, const __nv_bfloat16* __restrict__ Vl,
    __nv_bfloat16* __restrict__ Oh, __nv_bfloat16* __restrict__ Ol)
{
    extern __shared__ __align__(16) char dynsmem[];
    __nv_bfloat16* smp = (__nv_bfloat16*)dynsmem;

    const int tid  = threadIdx.x;
    const int lane = tid & 31;
    const int w    = tid >> 5;
    const int g    = lane >> 2;
    const int t    = lane & 3;

    const int qt = blockIdx.x, h = blockIdx.y, b = blockIdx.z;

    const unsigned lrow = lane & 7, lsel = lane >> 3;
    const unsigned frag = (lrow * 72 + 8 * lsel) * 2;   // pitch 72 bf16 = 144 B
    const unsigned base_u = s2u(smp);

    const int lr = tid >> 3;            // 0..15
    const int lc = (tid & 7) << 3;      // 0..56

    // ---- Q fragments in registers (constant across key loop) ----
    unsigned qfh[4][4], qfl[4][4];
    {
        const long qoff = ((long)(b * NQL + qt * 64 + w * 16)) * NIN + h * NDH;
        const __nv_bfloat16* qh = Qh + qoff;
        const __nv_bfloat16* ql = Ql + qoff;
#pragma unroll
        for (int j = 0; j < 4; j++) {
            int d0 = 16 * j + 2 * t;
            qfh[j][0] = *(const unsigned*)(qh + (long)g * NIN + d0);
            qfh[j][1] = *(const unsigned*)(qh + (long)(g + 8) * NIN + d0);
            qfh[j][2] = *(const unsigned*)(qh + (long)g * NIN + d0 + 8);
            qfh[j][3] = *(const unsigned*)(qh + (long)(g + 8) * NIN + d0 + 8);
            qfl[j][0] = *(const unsigned*)(ql + (long)g * NIN + d0);
            qfl[j][1] = *(const unsigned*)(ql + (long)(g + 8) * NIN + d0);
            qfl[j][2] = *(const unsigned*)(ql + (long)g * NIN + d0 + 8);
            qfl[j][3] = *(const unsigned*)(ql + (long)(g + 8) * NIN + d0 + 8);
        }
    }

    float o[8][4];
#pragma unroll
    for (int ct = 0; ct < 8; ct++)
#pragma unroll
        for (int e = 0; e < 4; e++) o[ct][e] = 0.f;
    float m0 = -1e30f, m1 = -1e30f, l0 = 0.f, l1 = 0.f;

    const __nv_bfloat16* kbh = Kh + (long)b * NKL * NIN + h * NDH;
    const __nv_bfloat16* kbl = Kl + (long)b * NKL * NIN + h * NDH;
    const __nv_bfloat16* vbh = Vh + (long)(b * NH + h) * NDH * NKL;
    const __nv_bfloat16* vbl = Vl + (long)(b * NH + h) * NDH * NKL;

    const int NKT = NKL / 64;
    AT_LOAD(0, 0);

    for (int kt = 0; kt < NKT; kt++) {
        if (kt + 1 < NKT) { AT_LOAD((kt + 1) & 1, kt + 1); CP_WAIT(1); }
        else              { CP_WAIT(0); }
        __syncthreads();

        const unsigned sb = base_u + (unsigned)(kt & 1) * (4 * AT_AS * 2);

        // ---- S = Q @ K^T (bf16x3) via ldmatrix.x4 ----
        float s[8][4];
#pragma unroll
        for (int nt = 0; nt < 8; nt++) {
            s[nt][0] = s[nt][1] = s[nt][2] = s[nt][3] = 0.f;
#pragma unroll
            for (int jp = 0; jp < 2; jp++) {
                const unsigned ka = sb + nt * 1152 + jp * 64 + frag;
                unsigned bh[4], bl[4];
                ldm_x4(bh, ka);
                ldm_x4(bl, ka + AT_AS * 2);
                mma_bf16(s[nt], qfh[2 * jp],     bh[0], bh[1]);
                mma_bf16(s[nt], qfh[2 * jp],     bl[0], bl[1]);
                mma_bf16(s[nt], qfl[2 * jp],     bh[0], bh[1]);
                mma_bf16(s[nt], qfh[2 * jp + 1], bh[2], bh[3]);
                mma_bf16(s[nt], qfh[2 * jp + 1], bl[2], bl[3]);
                mma_bf16(s[nt], qfl[2 * jp + 1], bh[2], bh[3]);
            }
        }

        // ---- online softmax ----
        float mt0 = -1e30f, mt1 = -1e30f;
#pragma unroll
        for (int nt = 0; nt < 8; nt++) {
            mt0 = fmaxf(mt0, fmaxf(s[nt][0], s[nt][1]));
            mt1 = fmaxf(mt1, fmaxf(s[nt][2], s[nt][3]));
        }
        mt0 = fmaxf(mt0, __shfl_xor_sync(0xffffffffu, mt0, 1));
        mt0 = fmaxf(mt0, __shfl_xor_sync(0xffffffffu, mt0, 2));
        mt1 = fmaxf(mt1, __shfl_xor_sync(0xffffffffu, mt1, 1));
        mt1 = fmaxf(mt1, __shfl_xor_sync(0xffffffffu, mt1, 2));
        float mn0 = fmaxf(m0, mt0), mn1 = fmaxf(m1, mt1);
        float cr0 = __expf(m0 - mn0), cr1 = __expf(m1 - mn1);
        m0 = mn0; m1 = mn1;

        float rs0 = 0.f, rs1 = 0.f;
        unsigned ph[8][2], pl[8][2];
#pragma unroll
        for (int nt = 0; nt < 8; nt++) {
            float p0 = __expf(s[nt][0] - m0), p1 = __expf(s[nt][1] - m0);
            float p2 = __expf(s[nt][2] - m1), p3 = __expf(s[nt][3] - m1);
            rs0 += p0 + p1; rs1 += p2 + p3;
            __nv_bfloat162 H, L;
            split1(p0, H.x, L.x); split1(p1, H.y, L.y);
            ph[nt][0] = *(unsigned*)&H; pl[nt][0] = *(unsigned*)&L;
            split1(p2, H.x, L.x); split1(p3, H.y, L.y);
            ph[nt][1] = *(unsigned*)&H; pl[nt][1] = *(unsigned*)&L;
        }
        rs0 += __shfl_xor_sync(0xffffffffu, rs0, 1);
        rs0 += __shfl_xor_sync(0xffffffffu, rs0, 2);
        rs1 += __shfl_xor_sync(0xffffffffu, rs1, 1);
        rs1 += __shfl_xor_sync(0xffffffffu, rs1, 2);
        l0 = l0 * cr0 + rs0;
        l1 = l1 * cr1 + rs1;
#pragma unroll
        for (int ct = 0; ct < 8; ct++) {
            o[ct][0] *= cr0; o[ct][1] *= cr0;
            o[ct][2] *= cr1; o[ct][3] *= cr1;
        }

        // ---- O += P @ V (bf16x3) via ldmatrix.x4 ----
#pragma unroll
        for (int jp = 0; jp < 2; jp++) {
            unsigned ah0[4] = {ph[4 * jp][0],     ph[4 * jp][1],
                               ph[4 * jp + 1][0], ph[4 * jp + 1][1]};
            unsigned al0[4] = {pl[4 * jp][0],     pl[4 * jp][1],
                               pl[4 * jp + 1][0], pl[4 * jp + 1][1]};
            unsigned ah1[4] = {ph[4 * jp + 2][0], ph[4 * jp + 2][1],
                               ph[4 * jp + 3][0], ph[4 * jp + 3][1]};
            unsigned al1[4] = {pl[4 * jp + 2][0], pl[4 * jp + 2][1],
                               pl[4 * jp + 3][0], pl[4 * jp + 3][1]};
#pragma unroll
            for (int ct = 0; ct < 8; ct++) {
                const unsigned va = sb + 2 * AT_AS * 2 + ct * 1152 + jp * 64 + frag;
                unsigned vh4[4], vl4[4];
                ldm_x4(vh4, va);
                ldm_x4(vl4, va + AT_AS * 2);
                mma_bf16(o[ct], ah0, vh4[0], vh4[1]);
                mma_bf16(o[ct], ah0, vl4[0], vl4[1]);
                mma_bf16(o[ct], al0, vh4[0], vh4[1]);
                mma_bf16(o[ct], ah1, vh4[2], vh4[3]);
                mma_bf16(o[ct], ah1, vl4[2], vl4[3]);
                mma_bf16(o[ct], al1, vh4[2], vh4[3]);
            }
        }
        __syncthreads();
    }

    // ---- epilogue: normalize, split to bf16 hi/lo, write Oh/Ol ----
    float i0 = 1.f / l0, i1 = 1.f / l1;
    const long obase = ((long)(b * NQL + qt * 64 + w * 16)) * NIN + h * NDH;
#pragma unroll
    for (int ct = 0; ct < 8; ct++) {
        int cc = 8 * ct + 2 * t;
        __nv_bfloat162 H, L;
        split1(o[ct][0] * i0, H.x, L.x);
        split1(o[ct][1] * i0, H.y, L.y);
        long o0 = obase + (long)g * NIN + cc;
        *(__nv_bfloat162*)(Oh + o0) = H;
        *(__nv_bfloat162*)(Ol + o0) = L;
        split1(o[ct][2] * i1, H.x, L.x);
        split1(o[ct][3] * i1, H.y, L.y);
        long o1 = obase + (long)(g + 8) * NIN + cc;
        *(__nv_bfloat162*)(Oh + o1) = H;
        *(__nv_bfloat162*)(Ol + o1) = L;
    }
}

// ---------------------------------------------------------------------------
// Launch pipeline (graph-capturable: kernel launches only)
// ---------------------------------------------------------------------------
extern "C" void kernel_launch(void* const* d_in, const int* in_sizes, int n_in,
                              void* d_out, int out_size)
{
    (void)in_sizes; (void)n_in; (void)out_size;
    const float* x   = (const float*)d_in[0];
    const float* ctx = (const float*)d_in[1];
    const float* Wq  = (const float*)d_in[2];
    const float* Wk  = (const float*)d_in[3];
    const float* Wv  = (const float*)d_in[4];
    const float* Wo  = (const float*)d_in[5];
    const float* bo  = (const float*)d_in[6];
    float* out = (float*)d_out;

    __nv_bfloat16 *Xh, *Xl, *Ch, *Cl, *Qh, *Ql, *Kh, *Kl, *Vh, *Vl, *Oh, *Ol;
    __nv_bfloat16 *Wqh, *Wql, *Wkh, *Wkl, *Wvh, *Wvl, *Woh, *Wol;
    cudaGetSymbolAddress((void**)&Xh, g_Xh);  cudaGetSymbolAddress((void**)&Xl, g_Xl);
    cudaGetSymbolAddress((void**)&Ch, g_Ch);  cudaGetSymbolAddress((void**)&Cl, g_Cl);
    cudaGetSymbolAddress((void**)&Qh, g_Qh);  cudaGetSymbolAddress((void**)&Ql, g_Ql);
    cudaGetSymbolAddress((void**)&Kh, g_Kh);  cudaGetSymbolAddress((void**)&Kl, g_Kl);
    cudaGetSymbolAddress((void**)&Vh, g_Vh);  cudaGetSymbolAddress((void**)&Vl, g_Vl);
    cudaGetSymbolAddress((void**)&Oh, g_Oh);  cudaGetSymbolAddress((void**)&Ol, g_Ol);
    cudaGetSymbolAddress((void**)&Wqh, g_Wqh); cudaGetSymbolAddress((void**)&Wql, g_Wql);
    cudaGetSymbolAddress((void**)&Wkh, g_Wkh); cudaGetSymbolAddress((void**)&Wkl, g_Wkl);
    cudaGetSymbolAddress((void**)&Wvh, g_Wvh); cudaGetSymbolAddress((void**)&Wvl, g_Wvl);
    cudaGetSymbolAddress((void**)&Woh, g_Woh); cudaGetSymbolAddress((void**)&Wol, g_Wol);

    // Allow >48KB dynamic smem (host attribute set; not a stream op)
    cudaFuncSetAttribute(gemm3_kernel<0>,
                         cudaFuncAttributeMaxDynamicSharedMemorySize, G3_SMEM);
    cudaFuncSetAttribute(gemm3_kernel<1>,
                         cudaFuncAttributeMaxDynamicSharedMemorySize, G3_SMEM);
    cudaFuncSetAttribute(gemm3_kernel<2>,
                         cudaFuncAttributeMaxDynamicSharedMemorySize, G3_SMEM);
    cudaFuncSetAttribute(attn_mma_kernel,
                         cudaFuncAttributeMaxDynamicSharedMemorySize, AT_SMEM);

    const int MTOK = NB * NQL;   // 8192 token rows

    // Input & weight hi/lo splits
    const int nx4 = (MTOK * NQD) / 4;
    const int nc4 = (MTOK * NCD) / 4;
    split_kernel<<<(nx4 + 255) / 256, 256>>>(x,   Xh, Xl, nx4);
    split_kernel<<<(nc4 + 255) / 256, 256>>>(ctx, Ch, Cl, nc4);
    dim3 wb(32, 8);
    wsplit_kernel<<<dim3(NQD / 32, NIN / 32), wb>>>(Wq, Wqh, Wql, NQD, NIN);
    wsplit_kernel<<<dim3(NCD / 32, NIN / 32), wb>>>(Wk, Wkh, Wkl, NCD, NIN);
    wsplit_kernel<<<dim3(NCD / 32, NIN / 32), wb>>>(Wv, Wvh, Wvl, NCD, NIN);
    wsplit_kernel<<<dim3(NIN / 32, NQD / 32), wb>>>(Wo, Woh, Wol, NIN, NQD);

    // Projections on tensor cores (bf16x3), epilogue-fused output formats
    dim3 gp(NIN / 128, MTOK / 128);
    gemm3_kernel<1><<<gp, 256, G3_SMEM>>>(Xh, Xl, Wqh, Wql, nullptr, nullptr,
                                          Qh, Ql, MTOK, NIN, NQD, ATTN_SCALE);
    gemm3_kernel<1><<<gp, 256, G3_SMEM>>>(Ch, Cl, Wkh, Wkl, nullptr, nullptr,
                                          Kh, Kl, MTOK, NIN, NCD, 1.0f);
    gemm3_kernel<2><<<gp, 256, G3_SMEM>>>(Ch, Cl, Wvh, Wvl, nullptr, nullptr,
                                          Vh, Vl, MTOK, NIN, NCD, 1.0f);

    // Flash attention on tensor cores (emits bf16-split O)
    dim3 ga(NQL / 64, NH, NB);
    attn_mma_kernel<<<ga, 128, AT_SMEM>>>(Qh, Ql, Kh, Kl, Vh, Vl, Oh, Ol);

    // Output projection with bias (fp32 result)
    dim3 go(NQD / 128, MTOK / 128);
    gemm3_kernel<0><<<go, 256, G3_SMEM>>>(Oh, Ol, Woh, Wol, bo, out,
                                          nullptr, nullptr, MTOK, NQD, NIN, 1.0f);
}